// round 12
// baseline (speedup 1.0000x reference)
#include <cuda_runtime.h>
#include <cuda_bf16.h>
#include <cstdint>

#define NNODES 8192
#define QK_STRIDE 512
#define NT_TOTAL 2048        // 4 nodes per tile (M=128)

// ------------------------------------------------------------------ scratch
// m-major layout: g_q/g_k[node*512 + m*64 + e], m in [0,8), e in [0,64)
__device__ __align__(16) float g_q[(size_t)NNODES * QK_STRIDE];
__device__ __align__(16) float g_k[(size_t)NNODES * QK_STRIDE];
// 2 tile-blocked fp16 weight images, 32KB each: [E][R]
__device__ __align__(16) unsigned char g_wtiles[2 * 32768];

// ------------------------------------------------------------------ helpers
__device__ __forceinline__ uint32_t smem_u32(const void* p) {
    uint32_t a;
    asm("{ .reg .u64 t; cvta.to.shared.u64 t, %1; cvt.u32.u64 %0, t; }" : "=r"(a) : "l"(p));
    return a;
}
__device__ __forceinline__ uint32_t pack_f16x2(float a, float b) {   // lo=f16(a), hi=f16(b)
    uint32_t p;
    asm("cvt.rn.f16x2.f32 %0, %1, %2;" : "=r"(p) : "f"(b), "f"(a));
    return p;
}
#define LDSM_X4(r0, r1, r2, r3, addr) \
    asm volatile("ldmatrix.sync.aligned.m8n8.x4.shared.b16 {%0,%1,%2,%3}, [%4];" \
        : "=r"(r0), "=r"(r1), "=r"(r2), "=r"(r3) : "r"(addr))
#define MMA_F16(c, a0, a1, a2, a3, b0, b1) \
    asm volatile("mma.sync.aligned.m16n8k16.row.col.f32.f16.f16.f32 " \
        "{%0,%1,%2,%3}, {%4,%5,%6,%7}, {%8,%9}, {%0,%1,%2,%3};" \
        : "+f"((c)[0]), "+f"((c)[1]), "+f"((c)[2]), "+f"((c)[3]) \
        : "r"(a0), "r"(a1), "r"(a2), "r"(a3), "r"(b0), "r"(b1))
#define CP_ASYNC16(saddr, gptr) \
    asm volatile("cp.async.cg.shared.global [%0], [%1], 16;" :: "r"(saddr), "l"(gptr))
#define CP_COMMIT() asm volatile("cp.async.commit_group;")
#define CP_WAIT0()  asm volatile("cp.async.wait_group 0;" ::: "memory")

// ------------------------------------------------------------------ main smem map (bytes)
#define SW_E   0          // 32768 fp16 edge image
#define SW_R   32768      // 32768 fp16 res image
#define SW_W0  65536      // 32768 fp16 W buf 0 (M=128)
#define SW_W1  98304      // 32768 fp16 W buf 1
#define SMEM_B 131072

// prep smem: [0:98304) weights tq|tk1|tk2 fp32, then x slots 16 x 1040 f32
#define PREP_SMEM (98304 + 16 * 1040 * 4)

// ------------------------------------------------------------------ kernel 0: prep = wsplit + proj
__global__ void __launch_bounds__(512) prep_kernel(
    const float* __restrict__ ew,  const float* __restrict__ rw,
    const float* __restrict__ x1,  const float* __restrict__ x2,
    const float* __restrict__ tq,  const float* __restrict__ tk1,
    const float* __restrict__ tk2)
{
    extern __shared__ char smem[];
    const int tid = threadIdx.x;
    if (blockIdx.x < 64) {
        // ---- weight conversion (edge/res GEMM B images, fp16)
        int id = blockIdx.x * 512 + tid;              // 0..32767
        int w = id >> 14, k = (id >> 7) & 127, n = id & 127;
        float v = (w ? rw : ew)[k * 128 + n];         // B[n][k] = W[k][n]
        uint32_t off = (uint32_t)(((n >> 3) * 8 + (k >> 4)) * 256 + (((k >> 3) & 1) << 7)
                                  + ((n & 7) << 4) + ((k & 7) << 1));
        uint32_t p = pack_f16x2(v, 0.f);
        *(uint16_t*)(g_wtiles + (size_t)w * 32768 + off) = (uint16_t)(p & 0xffffu);
        return;
    }
    // ---- projections: 32 nodes per block, 16 warps, 2 nodes per warp
    float* psm = (float*)smem;
    const uint32_t sb = smem_u32(smem);
    {
        #pragma unroll
        for (int i = 0; i < 4; ++i) {
            uint32_t off = (uint32_t)(i * 8192 + tid * 16);
            CP_ASYNC16(sb + off,           (const char*)tq  + off);
            CP_ASYNC16(sb + 32768u + off,  (const char*)tk1 + off);
            CP_ASYNC16(sb + 65536u + off,  (const char*)tk2 + off);
        }
        CP_COMMIT();
    }
    const int wid = tid >> 5, lane = tid & 31;
    float* sx = psm + 24576 + wid * 1040;
    const int nbase = (blockIdx.x - 64) * 32;
    CP_WAIT0();
    __syncthreads();

    const float2* wqp  = (const float2*)psm + lane;
    const float2* wk1p = (const float2*)(psm + 8192) + lane;
    const float2* wk2p = (const float2*)(psm + 16384) + lane;

    for (int it = 0; it < 2; ++it) {
        const int node = nbase + it * 16 + wid;
        const float* px1 = x1 + (size_t)node * 384;
        const float* px2 = x2 + (size_t)node * 640;
        for (int j = lane; j < 384; j += 32) { int d = j / 3; sx[d * 8 + (j - d * 3)] = __ldg(px1 + j); }
        for (int j = lane; j < 640; j += 32) { int d = j / 5; sx[d * 8 + 3 + (j - d * 5)] = __ldg(px2 + j); }
        __syncwarp();

        float aq[16], ak[16];   // [m][e0/e1], e0=2*lane, e1=2*lane+1
        #pragma unroll
        for (int i = 0; i < 16; ++i) { aq[i] = 0.f; ak[i] = 0.f; }
        #pragma unroll 4
        for (int d = 0; d < 128; ++d) {
            const float2 w_q = wqp[d * 32];
            const float2 w_1 = wk1p[d * 32];
            const float2 w_2 = wk2p[d * 32];
            const float2* xr = (const float2*)(sx + d * 8);
            float2 x01 = xr[0], x23 = xr[1], x45 = xr[2], x67 = xr[3];
            const float xs[8] = {x01.x, x01.y, x23.x, x23.y, x45.x, x45.y, x67.x, x67.y};
            #pragma unroll
            for (int m = 0; m < 8; ++m) {
                aq[m * 2]     += w_q.x * xs[m];
                aq[m * 2 + 1] += w_q.y * xs[m];
                const float wk0  = (m < 3) ? w_1.x : w_2.x;
                const float wk1v = (m < 3) ? w_1.y : w_2.y;
                ak[m * 2]     += wk0  * xs[m];
                ak[m * 2 + 1] += wk1v * xs[m];
            }
        }
        // m-major coalesced stores
        float* oq = g_q + (size_t)node * QK_STRIDE + 2 * lane;
        float* ok = g_k + (size_t)node * QK_STRIDE + 2 * lane;
        #pragma unroll
        for (int m = 0; m < 8; ++m) {
            *(float2*)(oq + m * 64) = make_float2(aq[m * 2], aq[m * 2 + 1]);
            *(float2*)(ok + m * 64) = make_float2(ak[m * 2], ak[m * 2 + 1]);
        }
        __syncwarp();
    }
}

// ------------------------------------------------------------------ LN macros (literal indices only)
#define LN_PREFETCH(KN, R) do { \
    const float* kp_ = kbase + (size_t)idxv[(R)] * 512; \
    _Pragma("unroll") \
    for (int mm = 0; mm < 8; ++mm) KN[mm] = __ldg((const float2*)(kp_ + mm * 64)); \
} while (0)

#define LN_COMPUTE_ROW(K, R) do { \
    float v0 = q[0].x*K[0].x + q[1].x*K[1].x + q[2].x*K[2].x; \
    float v1 = q[0].y*K[0].y + q[1].y*K[1].y + q[2].y*K[2].y; \
    float v2 = q[3].x*K[3].x + q[4].x*K[4].x + q[5].x*K[5].x + q[6].x*K[6].x + q[7].x*K[7].x; \
    float v3 = q[3].y*K[3].y + q[4].y*K[4].y + q[5].y*K[5].y + q[6].y*K[6].y + q[7].y*K[7].y; \
    float s_ = v0 + v1 + v2 + v3; \
    float ss_ = v0*v0 + v1*v1 + v2*v2 + v3*v3; \
    _Pragma("unroll") \
    for (int o_ = 16; o_ > 0; o_ >>= 1) { \
        s_  += __shfl_xor_sync(0xffffffffu, s_,  o_); \
        ss_ += __shfl_xor_sync(0xffffffffu, ss_, o_); \
    } \
    const float mu_ = s_ * (1.f / 128.f); \
    const float var_ = ss_ * (1.f / 128.f) - mu_ * mu_; \
    const float sc_ = rsqrtf(fmaxf(var_, 0.f) + 1e-5f); \
    v0 = (v0 - mu_) * sc_ * gl0; v1 = (v1 - mu_) * sc_ * gl1; \
    v2 = (v2 - mu_) * sc_ * gl2; v3 = (v3 - mu_) * sc_ * gl3; \
    const int m_ = m0 + (R); \
    const uint32_t off_ = (uint32_t)(((m_ >> 3) << 11) + ((m_ & 7) << 4) \
                                     + ((lane >> 2) << 7) + ((lane & 3) << 2)); \
    *(uint32_t*)(wbp + off_)         = pack_f16x2(v0, v1); \
    *(uint32_t*)(wbp + off_ + 1024u) = pack_f16x2(v2, v3); \
} while (0)

// ------------------------------------------------------------------ kernel 1: warp-specialized persistent main
__global__ void __launch_bounds__(512, 1) main_kernel(
    const float* __restrict__ t_ij, const int* __restrict__ nidx,
    const float* __restrict__ lnw, float* __restrict__ out)
{
    extern __shared__ char smem[];
    const uint32_t sb = smem_u32(smem);
    const int tid = threadIdx.x, lane = tid & 31, wid = tid >> 5;

    // ---- stage weight images ONCE (64 KB)
    {
        const char* gsrc = (const char*)g_wtiles;
        #pragma unroll
        for (int i = 0; i < 8; ++i) {
            uint32_t off = (uint32_t)(i * 8192 + tid * 16);
            CP_ASYNC16(sb + SW_E + off, gsrc + off);
        }
        CP_COMMIT();
    }
    const float gl0 = __ldg(lnw + 2 * lane), gl1 = __ldg(lnw + 2 * lane + 1);
    const float gl2 = __ldg(lnw + 64 + 2 * lane), gl3 = __ldg(lnw + 65 + 2 * lane);
    CP_WAIT0();
    __syncthreads();

    // GEMM-warp constants (wid < 8): wq = M quad, nq = N half
    const int wq = wid & 3;
    const int nq = wid >> 2;
    const int mbase = wq * 32;
    const uint32_t a_lane = (uint32_t)((((lane >> 3) & 1) << 11) + ((lane >> 4) << 7) + ((lane & 7) << 4));
    const uint32_t b_lane = (uint32_t)(((lane >> 4) << 11) + (((lane >> 3) & 1) << 7) + ((lane & 7) << 4));
    const int r0  = mbase + (lane >> 2);
    const int cbx = (lane & 3) * 2;
    // LN-warp constants (wid >= 8)
    const int pw = wid - 8;

    const int nloc = (blockIdx.x < NT_TOTAL) ? ((NT_TOTAL - 1 - (int)blockIdx.x) / (int)gridDim.x + 1) : 0;

    for (int i = 0; i <= nloc; ++i) {
        if (wid >= 8) {
            // ================= LN warps: produce W[i&1] for tile(i), rows pw*16..pw*16+15
            if (i < nloc) {
                const int tile = blockIdx.x + i * (int)gridDim.x;
                const int batch = tile >> 10;
                char* wbp = smem + ((i & 1) ? SW_W1 : SW_W0);
                const int m0 = pw * 16;
                const int node = tile * 4 + (m0 >> 5);

                // q for this warp's node (all 16 rows share it)
                const float* qp = g_q + (size_t)node * 512 + 2 * lane;
                float2 q[8];
                #pragma unroll
                for (int m = 0; m < 8; ++m) q[m] = __ldg((const float2*)(qp + m * 64));

                // neighbor indices (uniform loads)
                const int* ixp = nidx + tile * 128 + m0;
                int idxv[16];
                #pragma unroll
                for (int rr = 0; rr < 16; ++rr) idxv[rr] = __ldg(ixp + rr);

                const float* kbase = g_k + (size_t)batch * 4096 * 512 + 2 * lane;

                // row-pair interleaved pipeline, depth = 2 pairs
                float2 kA0[8], kA1[8], kB0[8], kB1[8];
                LN_PREFETCH(kA0, 0);  LN_PREFETCH(kA1, 1);
                LN_PREFETCH(kB0, 2);  LN_PREFETCH(kB1, 3);
                LN_COMPUTE_ROW(kA0, 0);   LN_COMPUTE_ROW(kA1, 1);
                LN_PREFETCH(kA0, 4);  LN_PREFETCH(kA1, 5);
                LN_COMPUTE_ROW(kB0, 2);   LN_COMPUTE_ROW(kB1, 3);
                LN_PREFETCH(kB0, 6);  LN_PREFETCH(kB1, 7);
                LN_COMPUTE_ROW(kA0, 4);   LN_COMPUTE_ROW(kA1, 5);
                LN_PREFETCH(kA0, 8);  LN_PREFETCH(kA1, 9);
                LN_COMPUTE_ROW(kB0, 6);   LN_COMPUTE_ROW(kB1, 7);
                LN_PREFETCH(kB0, 10); LN_PREFETCH(kB1, 11);
                LN_COMPUTE_ROW(kA0, 8);   LN_COMPUTE_ROW(kA1, 9);
                LN_PREFETCH(kA0, 12); LN_PREFETCH(kA1, 13);
                LN_COMPUTE_ROW(kB0, 10);  LN_COMPUTE_ROW(kB1, 11);
                LN_PREFETCH(kB0, 14); LN_PREFETCH(kB1, 15);
                LN_COMPUTE_ROW(kA0, 12);  LN_COMPUTE_ROW(kA1, 13);
                LN_COMPUTE_ROW(kB0, 14);  LN_COMPUTE_ROW(kB1, 15);
            }
        } else if (i >= 1) {
            // ================= GEMM warps: consume W[(i-1)&1] for tile(i-1)
            const int tile = blockIdx.x + (i - 1) * (int)gridDim.x;
            const uint32_t wb = sb + (((i - 1) & 1) ? SW_W1 : SW_W0);
            const float* tb = t_ij + (size_t)tile * 16384;
            float* ob = out + (size_t)tile * 16384;
            #pragma unroll 1
            for (int nh = 0; nh < 2; ++nh) {
                float accE[32], accR[32];
                #pragma unroll
                for (int z = 0; z < 32; ++z) { accE[z] = 0.f; accR[z] = 0.f; }
                // ---- edge GEMM: fp16 single pass (A = normalized W from smem)
                #pragma unroll
                for (int ks = 0; ks < 8; ++ks) {
                    uint32_t ah[8];
                    const uint32_t aoff = a_lane + (uint32_t)(ks * 256);
                    LDSM_X4(ah[0], ah[1], ah[2], ah[3], wb + (uint32_t)((4 * wq) * 2048) + aoff);
                    LDSM_X4(ah[4], ah[5], ah[6], ah[7], wb + (uint32_t)((4 * wq + 2) * 2048) + aoff);
                    #pragma unroll
                    for (int ntp = 0; ntp < 2; ++ntp) {
                        const uint32_t boff = (uint32_t)((nq * 8 + nh * 4 + ntp * 2) << 11) + b_lane + (uint32_t)(ks << 8);
                        uint32_t e0, e1, e2, e3;
                        LDSM_X4(e0, e1, e2, e3, sb + SW_E + boff);
                        MMA_F16(&accE[((0 * 2 + ntp) * 2 + 0) * 4], ah[0], ah[1], ah[2], ah[3], e0, e1);
                        MMA_F16(&accE[((0 * 2 + ntp) * 2 + 1) * 4], ah[0], ah[1], ah[2], ah[3], e2, e3);
                        MMA_F16(&accE[((1 * 2 + ntp) * 2 + 0) * 4], ah[4], ah[5], ah[6], ah[7], e0, e1);
                        MMA_F16(&accE[((1 * 2 + ntp) * 2 + 1) * 4], ah[4], ah[5], ah[6], ah[7], e2, e3);
                    }
                }
                // ---- res GEMM: fp16 single pass (A = T from global)
                #pragma unroll
                for (int ks = 0; ks < 8; ++ks) {
                    uint32_t th[8];
                    const int col = ks * 16 + cbx;
                    #pragma unroll
                    for (int mi = 0; mi < 2; ++mi) {
                        const int rr = r0 + mi * 16;
                        float2 v0 = __ldg((const float2*)(tb + rr * 128 + col));
                        float2 v1 = __ldg((const float2*)(tb + (rr + 8) * 128 + col));
                        float2 v2 = __ldg((const float2*)(tb + rr * 128 + col + 8));
                        float2 v3 = __ldg((const float2*)(tb + (rr + 8) * 128 + col + 8));
                        th[mi * 4 + 0] = pack_f16x2(v0.x, v0.y);
                        th[mi * 4 + 1] = pack_f16x2(v1.x, v1.y);
                        th[mi * 4 + 2] = pack_f16x2(v2.x, v2.y);
                        th[mi * 4 + 3] = pack_f16x2(v3.x, v3.y);
                    }
                    #pragma unroll
                    for (int ntp = 0; ntp < 2; ++ntp) {
                        const uint32_t boff = (uint32_t)((nq * 8 + nh * 4 + ntp * 2) << 11) + b_lane + (uint32_t)(ks << 8);
                        uint32_t b0, b1, b2, b3;
                        LDSM_X4(b0, b1, b2, b3, sb + SW_R + boff);
                        MMA_F16(&accR[((0 * 2 + ntp) * 2 + 0) * 4], th[0], th[1], th[2], th[3], b0, b1);
                        MMA_F16(&accR[((0 * 2 + ntp) * 2 + 1) * 4], th[0], th[1], th[2], th[3], b2, b3);
                        MMA_F16(&accR[((1 * 2 + ntp) * 2 + 0) * 4], th[4], th[5], th[6], th[7], b0, b1);
                        MMA_F16(&accR[((1 * 2 + ntp) * 2 + 1) * 4], th[4], th[5], th[6], th[7], b2, b3);
                    }
                }
                // ---- epilogue
                #pragma unroll
                for (int mi = 0; mi < 2; ++mi) {
                    #pragma unroll
                    for (int ntp = 0; ntp < 2; ++ntp) {
                        #pragma unroll
                        for (int sub = 0; sub < 2; ++sub) {
                            const int g4 = ((mi * 2 + ntp) * 2 + sub) * 4;
                            const int rr = r0 + mi * 16;
                            const int col = nq * 64 + nh * 32 + ntp * 16 + sub * 8 + cbx;
                            float o0 = 1.f / (1.f + __expf(-accE[g4 + 0])) + accR[g4 + 0];
                            float o1 = 1.f / (1.f + __expf(-accE[g4 + 1])) + accR[g4 + 1];
                            float o2 = 1.f / (1.f + __expf(-accE[g4 + 2])) + accR[g4 + 2];
                            float o3 = 1.f / (1.f + __expf(-accE[g4 + 3])) + accR[g4 + 3];
                            *(float2*)(ob + rr * 128 + col)       = make_float2(o0, o1);
                            *(float2*)(ob + (rr + 8) * 128 + col) = make_float2(o2, o3);
                        }
                    }
                }
            }
        }
        __syncthreads();   // pipeline step: swap W buffers
    }
}

// ------------------------------------------------------------------ launch
extern "C" void kernel_launch(void* const* d_in, const int* in_sizes, int n_in,
                              void* d_out, int out_size)
{
    const float* t_ij = (const float*)d_in[0];
    const float* x1   = (const float*)d_in[1];
    const float* x2   = (const float*)d_in[2];
    const int*   nidx = (const int*)  d_in[3];
    const float* tq   = (const float*)d_in[4];
    const float* tk1  = (const float*)d_in[5];
    const float* tk2  = (const float*)d_in[6];
    const float* lnw  = (const float*)d_in[7];
    const float* ew   = (const float*)d_in[8];
    const float* rw   = (const float*)d_in[9];
    float* out = (float*)d_out;

    int dev = 0, nsm = 148;
    cudaGetDevice(&dev);
    cudaDeviceGetAttribute(&nsm, cudaDevAttrMultiProcessorCount, dev);

    cudaFuncSetAttribute(prep_kernel, cudaFuncAttributeMaxDynamicSharedMemorySize, PREP_SMEM);
    cudaFuncSetAttribute(main_kernel, cudaFuncAttributeMaxDynamicSharedMemorySize, SMEM_B);

    prep_kernel<<<64 + NNODES / 32, 512, PREP_SMEM>>>(ew, rw, x1, x2, tq, tk1, tk2);
    main_kernel<<<nsm, 512, SMEM_B>>>(t_ij, nidx, lnw, out);
}

// round 13
// speedup vs baseline: 1.0686x; 1.0686x over previous
#include <cuda_runtime.h>
#include <cuda_bf16.h>
#include <cstdint>

#define NNODES 8192
#define QK_STRIDE 512
#define NT_TOTAL 2048        // 4 nodes per tile (M=128)

// ------------------------------------------------------------------ scratch
// m-major layout: g_q/g_k[node*512 + m*64 + e], m in [0,8), e in [0,64)
__device__ __align__(16) float g_q[(size_t)NNODES * QK_STRIDE];
__device__ __align__(16) float g_k[(size_t)NNODES * QK_STRIDE];
// 2 tile-blocked fp16 weight images, 32KB each: [E][R]
__device__ __align__(16) unsigned char g_wtiles[2 * 32768];

// ------------------------------------------------------------------ helpers
__device__ __forceinline__ uint32_t smem_u32(const void* p) {
    uint32_t a;
    asm("{ .reg .u64 t; cvta.to.shared.u64 t, %1; cvt.u32.u64 %0, t; }" : "=r"(a) : "l"(p));
    return a;
}
__device__ __forceinline__ uint32_t pack_f16x2(float a, float b) {   // lo=f16(a), hi=f16(b)
    uint32_t p;
    asm("cvt.rn.f16x2.f32 %0, %1, %2;" : "=r"(p) : "f"(b), "f"(a));
    return p;
}
#define LDSM_X4(r0, r1, r2, r3, addr) \
    asm volatile("ldmatrix.sync.aligned.m8n8.x4.shared.b16 {%0,%1,%2,%3}, [%4];" \
        : "=r"(r0), "=r"(r1), "=r"(r2), "=r"(r3) : "r"(addr))
#define MMA_F16(c, a0, a1, a2, a3, b0, b1) \
    asm volatile("mma.sync.aligned.m16n8k16.row.col.f32.f16.f16.f32 " \
        "{%0,%1,%2,%3}, {%4,%5,%6,%7}, {%8,%9}, {%0,%1,%2,%3};" \
        : "+f"((c)[0]), "+f"((c)[1]), "+f"((c)[2]), "+f"((c)[3]) \
        : "r"(a0), "r"(a1), "r"(a2), "r"(a3), "r"(b0), "r"(b1))
#define CP_ASYNC16(saddr, gptr) \
    asm volatile("cp.async.cg.shared.global [%0], [%1], 16;" :: "r"(saddr), "l"(gptr))
#define CP_COMMIT() asm volatile("cp.async.commit_group;")
#define CP_WAIT0()  asm volatile("cp.async.wait_group 0;" ::: "memory")

// ------------------------------------------------------------------ main smem map (bytes)
#define SW_E   0          // 32768 fp16 edge image
#define SW_R   32768      // 32768 fp16 res image
#define SW_W0  65536      // 32768 fp16 W buf 0 (M=128)
#define SW_W1  98304      // 32768 fp16 W buf 1
#define SMEM_B 131072

// prep smem: [0:98304) weights tq|tk1|tk2 fp32, then x slots 16 x 1040 f32
#define PREP_SMEM (98304 + 16 * 1040 * 4)

// ------------------------------------------------------------------ kernel 0: prep = wsplit + proj
__global__ void __launch_bounds__(512) prep_kernel(
    const float* __restrict__ ew,  const float* __restrict__ rw,
    const float* __restrict__ x1,  const float* __restrict__ x2,
    const float* __restrict__ tq,  const float* __restrict__ tk1,
    const float* __restrict__ tk2)
{
    extern __shared__ char smem[];
    const int tid = threadIdx.x;
    if (blockIdx.x < 64) {
        // ---- weight conversion (edge/res GEMM B images, fp16)
        int id = blockIdx.x * 512 + tid;              // 0..32767
        int w = id >> 14, k = (id >> 7) & 127, n = id & 127;
        float v = (w ? rw : ew)[k * 128 + n];         // B[n][k] = W[k][n]
        uint32_t off = (uint32_t)(((n >> 3) * 8 + (k >> 4)) * 256 + (((k >> 3) & 1) << 7)
                                  + ((n & 7) << 4) + ((k & 7) << 1));
        uint32_t p = pack_f16x2(v, 0.f);
        *(uint16_t*)(g_wtiles + (size_t)w * 32768 + off) = (uint16_t)(p & 0xffffu);
        return;
    }
    // ---- projections: 32 nodes per block, 16 warps, 2 nodes per warp
    float* psm = (float*)smem;
    const uint32_t sb = smem_u32(smem);
    {
        #pragma unroll
        for (int i = 0; i < 4; ++i) {
            uint32_t off = (uint32_t)(i * 8192 + tid * 16);
            CP_ASYNC16(sb + off,           (const char*)tq  + off);
            CP_ASYNC16(sb + 32768u + off,  (const char*)tk1 + off);
            CP_ASYNC16(sb + 65536u + off,  (const char*)tk2 + off);
        }
        CP_COMMIT();
    }
    const int wid = tid >> 5, lane = tid & 31;
    float* sx = psm + 24576 + wid * 1040;
    const int nbase = (blockIdx.x - 64) * 32;
    CP_WAIT0();
    __syncthreads();

    const float2* wqp  = (const float2*)psm + lane;
    const float2* wk1p = (const float2*)(psm + 8192) + lane;
    const float2* wk2p = (const float2*)(psm + 16384) + lane;

    for (int it = 0; it < 2; ++it) {
        const int node = nbase + it * 16 + wid;
        const float* px1 = x1 + (size_t)node * 384;
        const float* px2 = x2 + (size_t)node * 640;
        for (int j = lane; j < 384; j += 32) { int d = j / 3; sx[d * 8 + (j - d * 3)] = __ldg(px1 + j); }
        for (int j = lane; j < 640; j += 32) { int d = j / 5; sx[d * 8 + 3 + (j - d * 5)] = __ldg(px2 + j); }
        __syncwarp();

        float aq[16], ak[16];   // [m][e0/e1], e0=2*lane, e1=2*lane+1
        #pragma unroll
        for (int i = 0; i < 16; ++i) { aq[i] = 0.f; ak[i] = 0.f; }
        #pragma unroll 4
        for (int d = 0; d < 128; ++d) {
            const float2 w_q = wqp[d * 32];
            const float2 w_1 = wk1p[d * 32];
            const float2 w_2 = wk2p[d * 32];
            const float2* xr = (const float2*)(sx + d * 8);
            float2 x01 = xr[0], x23 = xr[1], x45 = xr[2], x67 = xr[3];
            const float xs[8] = {x01.x, x01.y, x23.x, x23.y, x45.x, x45.y, x67.x, x67.y};
            #pragma unroll
            for (int m = 0; m < 8; ++m) {
                aq[m * 2]     += w_q.x * xs[m];
                aq[m * 2 + 1] += w_q.y * xs[m];
                const float wk0  = (m < 3) ? w_1.x : w_2.x;
                const float wk1v = (m < 3) ? w_1.y : w_2.y;
                ak[m * 2]     += wk0  * xs[m];
                ak[m * 2 + 1] += wk1v * xs[m];
            }
        }
        // m-major coalesced stores
        float* oq = g_q + (size_t)node * QK_STRIDE + 2 * lane;
        float* ok = g_k + (size_t)node * QK_STRIDE + 2 * lane;
        #pragma unroll
        for (int m = 0; m < 8; ++m) {
            *(float2*)(oq + m * 64) = make_float2(aq[m * 2], aq[m * 2 + 1]);
            *(float2*)(ok + m * 64) = make_float2(ak[m * 2], ak[m * 2 + 1]);
        }
        __syncwarp();
    }
}

// ------------------------------------------------------------------ kernel 1: warp-specialized persistent main (1024 thr)
__global__ void __launch_bounds__(1024, 1) main_kernel(
    const float* __restrict__ t_ij, const int* __restrict__ nidx,
    const float* __restrict__ lnw, float* __restrict__ out)
{
    extern __shared__ char smem[];
    const uint32_t sb = smem_u32(smem);
    const int tid = threadIdx.x, lane = tid & 31, wid = tid >> 5;

    // ---- stage weight images ONCE (64 KB)
    {
        const char* gsrc = (const char*)g_wtiles;
        #pragma unroll
        for (int i = 0; i < 4; ++i) {
            uint32_t off = (uint32_t)(i * 16384 + tid * 16);
            CP_ASYNC16(sb + SW_E + off, gsrc + off);
        }
        CP_COMMIT();
    }
    const float gl0 = __ldg(lnw + 2 * lane), gl1 = __ldg(lnw + 2 * lane + 1);
    const float gl2 = __ldg(lnw + 64 + 2 * lane), gl3 = __ldg(lnw + 65 + 2 * lane);
    CP_WAIT0();
    __syncthreads();

    // GEMM-warp constants (wid < 16): wq = M quad, nq = N quarter
    const int wq = wid & 3;
    const int nq = (wid >> 2) & 3;
    const uint32_t a_lane = (uint32_t)((((lane >> 3) & 1) << 11) + ((lane >> 4) << 7) + ((lane & 7) << 4));
    const uint32_t b_lane = (uint32_t)(((lane >> 4) << 11) + (((lane >> 3) & 1) << 7) + ((lane & 7) << 4));
    const int r0  = wq * 32 + (lane >> 2);
    const int cbx = (lane & 3) * 2;

    const int nloc = (blockIdx.x < NT_TOTAL) ? ((NT_TOTAL - 1 - (int)blockIdx.x) / (int)gridDim.x + 1) : 0;

    for (int i = 0; i <= nloc; ++i) {
        if (wid >= 16) {
            // ================= LN warps: produce W[i&1] for tile(i), rows (wid-16)*8 .. +7
            if (i < nloc) {
                const int tile = blockIdx.x + i * (int)gridDim.x;
                const int batch = tile >> 10;
                char* wbp = smem + ((i & 1) ? SW_W1 : SW_W0);
                const int m0 = (wid - 16) * 8;
                const int node = tile * 4 + (m0 >> 5);

                const float* qp = g_q + (size_t)node * 512 + 2 * lane;
                float2 q[8];
                #pragma unroll
                for (int m = 0; m < 8; ++m) q[m] = __ldg((const float2*)(qp + m * 64));

                const int* ixp = nidx + tile * 128 + m0;
                const float* kbase = g_k + (size_t)batch * 4096 * 512 + 2 * lane;

                float2 kn[8];
                {
                    const float* kp = kbase + (size_t)__ldg(ixp) * 512;
                    #pragma unroll
                    for (int m = 0; m < 8; ++m) kn[m] = __ldg((const float2*)(kp + m * 64));
                }
                #pragma unroll
                for (int rr = 0; rr < 8; ++rr) {
                    float2 kc[8];
                    #pragma unroll
                    for (int m = 0; m < 8; ++m) kc[m] = kn[m];
                    if (rr < 7) {
                        const float* kp = kbase + (size_t)__ldg(ixp + rr + 1) * 512;
                        #pragma unroll
                        for (int m = 0; m < 8; ++m) kn[m] = __ldg((const float2*)(kp + m * 64));
                    }
                    float v0 = q[0].x*kc[0].x + q[1].x*kc[1].x + q[2].x*kc[2].x;
                    float v1 = q[0].y*kc[0].y + q[1].y*kc[1].y + q[2].y*kc[2].y;
                    float v2 = q[3].x*kc[3].x + q[4].x*kc[4].x + q[5].x*kc[5].x + q[6].x*kc[6].x + q[7].x*kc[7].x;
                    float v3 = q[3].y*kc[3].y + q[4].y*kc[4].y + q[5].y*kc[5].y + q[6].y*kc[6].y + q[7].y*kc[7].y;
                    float s  = v0 + v1 + v2 + v3;
                    float ss = v0*v0 + v1*v1 + v2*v2 + v3*v3;
                    #pragma unroll
                    for (int o = 16; o > 0; o >>= 1) {
                        s  += __shfl_xor_sync(0xffffffffu, s,  o);
                        ss += __shfl_xor_sync(0xffffffffu, ss, o);
                    }
                    const float mu = s * (1.f / 128.f);
                    const float var = ss * (1.f / 128.f) - mu * mu;
                    const float sc = rsqrtf(fmaxf(var, 0.f) + 1e-5f);
                    v0 = (v0 - mu) * sc * gl0; v1 = (v1 - mu) * sc * gl1;
                    v2 = (v2 - mu) * sc * gl2; v3 = (v3 - mu) * sc * gl3;
                    const int m = m0 + rr;
                    const uint32_t off1 = (uint32_t)(((m >> 3) << 11) + ((m & 7) << 4)
                                                     + ((lane >> 2) << 7) + ((lane & 3) << 2));
                    *(uint32_t*)(wbp + off1)         = pack_f16x2(v0, v1);
                    *(uint32_t*)(wbp + off1 + 1024u) = pack_f16x2(v2, v3);
                }
            }
        } else if (i >= 1) {
            // ================= GEMM warps: consume W[(i-1)&1] for tile(i-1)
            // acc = sigmoid(W @ E) computed first, then T @ R accumulated on top.
            const int tile = blockIdx.x + (i - 1) * (int)gridDim.x;
            const uint32_t wb = sb + (((i - 1) & 1) ? SW_W1 : SW_W0);
            const float* tb = t_ij + (size_t)tile * 16384;
            float* ob = out + (size_t)tile * 16384;

            float acc[32];
            #pragma unroll
            for (int z = 0; z < 32; ++z) acc[z] = 0.f;

            // ---- edge GEMM: fp16 (A = normalized W from smem)
            #pragma unroll
            for (int ks = 0; ks < 8; ++ks) {
                uint32_t ah[8];
                const uint32_t aoff = a_lane + (uint32_t)(ks * 256);
                LDSM_X4(ah[0], ah[1], ah[2], ah[3], wb + (uint32_t)((4 * wq) * 2048) + aoff);
                LDSM_X4(ah[4], ah[5], ah[6], ah[7], wb + (uint32_t)((4 * wq + 2) * 2048) + aoff);
                #pragma unroll
                for (int ntp = 0; ntp < 2; ++ntp) {
                    const uint32_t boff = (uint32_t)((nq * 4 + ntp * 2) << 11) + b_lane + (uint32_t)(ks << 8);
                    uint32_t e0, e1, e2, e3;
                    LDSM_X4(e0, e1, e2, e3, sb + SW_E + boff);
                    MMA_F16(&acc[((0 * 2 + ntp) * 2 + 0) * 4], ah[0], ah[1], ah[2], ah[3], e0, e1);
                    MMA_F16(&acc[((0 * 2 + ntp) * 2 + 1) * 4], ah[0], ah[1], ah[2], ah[3], e2, e3);
                    MMA_F16(&acc[((1 * 2 + ntp) * 2 + 0) * 4], ah[4], ah[5], ah[6], ah[7], e0, e1);
                    MMA_F16(&acc[((1 * 2 + ntp) * 2 + 1) * 4], ah[4], ah[5], ah[6], ah[7], e2, e3);
                }
            }
            // ---- sigmoid in place
            #pragma unroll
            for (int z = 0; z < 32; ++z) acc[z] = 1.f / (1.f + __expf(-acc[z]));

            // ---- res GEMM: fp16, accumulates onto sigmoid values
            #pragma unroll
            for (int ks = 0; ks < 8; ++ks) {
                uint32_t th[8];
                const int col = ks * 16 + cbx;
                #pragma unroll
                for (int mi = 0; mi < 2; ++mi) {
                    const int rr = r0 + mi * 16;
                    float2 v0 = __ldg((const float2*)(tb + rr * 128 + col));
                    float2 v1 = __ldg((const float2*)(tb + (rr + 8) * 128 + col));
                    float2 v2 = __ldg((const float2*)(tb + rr * 128 + col + 8));
                    float2 v3 = __ldg((const float2*)(tb + (rr + 8) * 128 + col + 8));
                    th[mi * 4 + 0] = pack_f16x2(v0.x, v0.y);
                    th[mi * 4 + 1] = pack_f16x2(v1.x, v1.y);
                    th[mi * 4 + 2] = pack_f16x2(v2.x, v2.y);
                    th[mi * 4 + 3] = pack_f16x2(v3.x, v3.y);
                }
                #pragma unroll
                for (int ntp = 0; ntp < 2; ++ntp) {
                    const uint32_t boff = (uint32_t)((nq * 4 + ntp * 2) << 11) + b_lane + (uint32_t)(ks << 8);
                    uint32_t b0, b1, b2, b3;
                    LDSM_X4(b0, b1, b2, b3, sb + SW_R + boff);
                    MMA_F16(&acc[((0 * 2 + ntp) * 2 + 0) * 4], th[0], th[1], th[2], th[3], b0, b1);
                    MMA_F16(&acc[((0 * 2 + ntp) * 2 + 1) * 4], th[0], th[1], th[2], th[3], b2, b3);
                    MMA_F16(&acc[((1 * 2 + ntp) * 2 + 0) * 4], th[4], th[5], th[6], th[7], b0, b1);
                    MMA_F16(&acc[((1 * 2 + ntp) * 2 + 1) * 4], th[4], th[5], th[6], th[7], b2, b3);
                }
            }
            // ---- store (values already final)
            #pragma unroll
            for (int mi = 0; mi < 2; ++mi) {
                #pragma unroll
                for (int ntp = 0; ntp < 2; ++ntp) {
                    #pragma unroll
                    for (int sub = 0; sub < 2; ++sub) {
                        const int g4 = ((mi * 2 + ntp) * 2 + sub) * 4;
                        const int rr = r0 + mi * 16;
                        const int col = nq * 32 + ntp * 16 + sub * 8 + cbx;
                        *(float2*)(ob + rr * 128 + col)       = make_float2(acc[g4 + 0], acc[g4 + 1]);
                        *(float2*)(ob + (rr + 8) * 128 + col) = make_float2(acc[g4 + 2], acc[g4 + 3]);
                    }
                }
            }
        }
        __syncthreads();   // pipeline step: swap W buffers
    }
}

// ------------------------------------------------------------------ launch
extern "C" void kernel_launch(void* const* d_in, const int* in_sizes, int n_in,
                              void* d_out, int out_size)
{
    const float* t_ij = (const float*)d_in[0];
    const float* x1   = (const float*)d_in[1];
    const float* x2   = (const float*)d_in[2];
    const int*   nidx = (const int*)  d_in[3];
    const float* tq   = (const float*)d_in[4];
    const float* tk1  = (const float*)d_in[5];
    const float* tk2  = (const float*)d_in[6];
    const float* lnw  = (const float*)d_in[7];
    const float* ew   = (const float*)d_in[8];
    const float* rw   = (const float*)d_in[9];
    float* out = (float*)d_out;

    int dev = 0, nsm = 148;
    cudaGetDevice(&dev);
    cudaDeviceGetAttribute(&nsm, cudaDevAttrMultiProcessorCount, dev);

    cudaFuncSetAttribute(prep_kernel, cudaFuncAttributeMaxDynamicSharedMemorySize, PREP_SMEM);
    cudaFuncSetAttribute(main_kernel, cudaFuncAttributeMaxDynamicSharedMemorySize, SMEM_B);

    prep_kernel<<<64 + NNODES / 32, 512, PREP_SMEM>>>(ew, rw, x1, x2, tq, tk1, tk2);
    main_kernel<<<nsm, 1024, SMEM_B>>>(t_ij, nidx, lnw, out);
}

// round 14
// speedup vs baseline: 1.0859x; 1.0161x over previous
#include <cuda_runtime.h>
#include <cuda_bf16.h>
#include <cstdint>

#define NNODES 8192
#define QK_STRIDE 512
#define NT_TOTAL 2048        // 4 nodes per tile (M=128)

// ------------------------------------------------------------------ scratch
// m-major layout: g_q/g_k[node*512 + m*64 + e], m in [0,8), e in [0,64)
__device__ __align__(16) float g_q[(size_t)NNODES * QK_STRIDE];
__device__ __align__(16) float g_k[(size_t)NNODES * QK_STRIDE];
// 2 tile-blocked fp16 weight images, 32KB each: [E][R]
__device__ __align__(16) unsigned char g_wtiles[2 * 32768];

// ------------------------------------------------------------------ helpers
__device__ __forceinline__ uint32_t smem_u32(const void* p) {
    uint32_t a;
    asm("{ .reg .u64 t; cvta.to.shared.u64 t, %1; cvt.u32.u64 %0, t; }" : "=r"(a) : "l"(p));
    return a;
}
__device__ __forceinline__ uint32_t pack_f16x2(float a, float b) {   // lo=f16(a), hi=f16(b)
    uint32_t p;
    asm("cvt.rn.f16x2.f32 %0, %1, %2;" : "=r"(p) : "f"(b), "f"(a));
    return p;
}
// packed fp32x2 FMA: d = a*b + d (elementwise on two packed fp32 lanes)
__device__ __forceinline__ void fma2(uint64_t& d, uint64_t a, uint64_t b) {
    asm("fma.rn.f32x2 %0, %1, %2, %0;" : "+l"(d) : "l"(a), "l"(b));
}
__device__ __forceinline__ uint64_t dup_f32x2(float x) {             // (x, x)
    uint64_t r;
    uint32_t xu = __float_as_uint(x);
    asm("mov.b64 %0, {%1, %1};" : "=l"(r) : "r"(xu));
    return r;
}
#define LDSM_X4(r0, r1, r2, r3, addr) \
    asm volatile("ldmatrix.sync.aligned.m8n8.x4.shared.b16 {%0,%1,%2,%3}, [%4];" \
        : "=r"(r0), "=r"(r1), "=r"(r2), "=r"(r3) : "r"(addr))
#define MMA_F16(c, a0, a1, a2, a3, b0, b1) \
    asm volatile("mma.sync.aligned.m16n8k16.row.col.f32.f16.f16.f32 " \
        "{%0,%1,%2,%3}, {%4,%5,%6,%7}, {%8,%9}, {%0,%1,%2,%3};" \
        : "+f"((c)[0]), "+f"((c)[1]), "+f"((c)[2]), "+f"((c)[3]) \
        : "r"(a0), "r"(a1), "r"(a2), "r"(a3), "r"(b0), "r"(b1))
#define CP_ASYNC16(saddr, gptr) \
    asm volatile("cp.async.cg.shared.global [%0], [%1], 16;" :: "r"(saddr), "l"(gptr))
#define CP_COMMIT() asm volatile("cp.async.commit_group;")
#define CP_WAIT0()  asm volatile("cp.async.wait_group 0;" ::: "memory")

// ------------------------------------------------------------------ main smem map (bytes)
#define SW_E   0          // 32768 fp16 edge image
#define SW_R   32768      // 32768 fp16 res image
#define SW_W0  65536      // 32768 fp16 W buf 0 (M=128)
#define SW_W1  98304      // 32768 fp16 W buf 1
#define SMEM_B 131072

// prep smem: [0:98304) weights tq|tk1|tk2 fp32, then x slots 16 warps x 2 nodes x 1024 f32
#define PREP_SMEM (98304 + 16 * 2048 * 4)

// ------------------------------------------------------------------ kernel 0: prep = wconv + proj (f32x2)
__global__ void __launch_bounds__(512) prep_kernel(
    const float* __restrict__ ew,  const float* __restrict__ rw,
    const float* __restrict__ x1,  const float* __restrict__ x2,
    const float* __restrict__ tq,  const float* __restrict__ tk1,
    const float* __restrict__ tk2)
{
    extern __shared__ char smem[];
    const int tid = threadIdx.x;
    if (blockIdx.x < 64) {
        // ---- weight conversion (edge/res GEMM B images, fp16)
        int id = blockIdx.x * 512 + tid;              // 0..32767
        int w = id >> 14, k = (id >> 7) & 127, n = id & 127;
        float v = (w ? rw : ew)[k * 128 + n];         // B[n][k] = W[k][n]
        uint32_t off = (uint32_t)(((n >> 3) * 8 + (k >> 4)) * 256 + (((k >> 3) & 1) << 7)
                                  + ((n & 7) << 4) + ((k & 7) << 1));
        uint32_t p = pack_f16x2(v, 0.f);
        *(uint16_t*)(g_wtiles + (size_t)w * 32768 + off) = (uint16_t)(p & 0xffffu);
        return;
    }
    // ---- projections: 32 nodes per block, 16 warps, 2 nodes per warp (one fused d-loop)
    float* psm = (float*)smem;
    const uint32_t sb = smem_u32(smem);
    {
        #pragma unroll
        for (int i = 0; i < 4; ++i) {
            uint32_t off = (uint32_t)(i * 8192 + tid * 16);
            CP_ASYNC16(sb + off,           (const char*)tq  + off);
            CP_ASYNC16(sb + 32768u + off,  (const char*)tk1 + off);
            CP_ASYNC16(sb + 65536u + off,  (const char*)tk2 + off);
        }
        CP_COMMIT();
    }
    const int wid = tid >> 5, lane = tid & 31;
    float* sx = psm + 24576 + wid * 2048;         // two node buffers of 1024 floats
    const int nbase = (blockIdx.x - 64) * 32;
    const int node0 = nbase + wid * 2;
    CP_WAIT0();
    __syncthreads();

    // stage x for both nodes: [d*8 + m], m 0..2 from x1, m 3..7 from x2
    #pragma unroll
    for (int n = 0; n < 2; ++n) {
        const float* px1 = x1 + (size_t)(node0 + n) * 384;
        const float* px2 = x2 + (size_t)(node0 + n) * 640;
        float* dst = sx + n * 1024;
        for (int j = lane; j < 384; j += 32) { int d = j / 3; dst[d * 8 + (j - d * 3)] = __ldg(px1 + j); }
        for (int j = lane; j < 640; j += 32) { int d = j / 5; dst[d * 8 + 3 + (j - d * 5)] = __ldg(px2 + j); }
    }
    __syncwarp();

    // packed accumulators: [node][m] of (e0,e1) = (2*lane, 2*lane+1)
    uint64_t aq[2][8], ak[2][8];
    #pragma unroll
    for (int n = 0; n < 2; ++n)
        #pragma unroll
        for (int m = 0; m < 8; ++m) { aq[n][m] = 0ull; ak[n][m] = 0ull; }

    const float* wq_b  = psm + 2 * lane;
    const float* wk1_b = psm + 8192 + 2 * lane;
    const float* wk2_b = psm + 16384 + 2 * lane;

    #pragma unroll 4
    for (int d = 0; d < 128; ++d) {
        const uint64_t wq2 = *(const uint64_t*)(wq_b  + d * 64);
        const uint64_t w12 = *(const uint64_t*)(wk1_b + d * 64);
        const uint64_t w22 = *(const uint64_t*)(wk2_b + d * 64);
        #pragma unroll
        for (int n = 0; n < 2; ++n) {
            const float* xr = sx + n * 1024 + d * 8;
            const float4 xa = *(const float4*)xr;
            const float4 xb = *(const float4*)(xr + 4);
            const float xs[8] = {xa.x, xa.y, xa.z, xa.w, xb.x, xb.y, xb.z, xb.w};
            #pragma unroll
            for (int m = 0; m < 8; ++m) {
                const uint64_t xx = dup_f32x2(xs[m]);
                fma2(aq[n][m], wq2, xx);
                fma2(ak[n][m], (m < 3) ? w12 : w22, xx);
            }
        }
    }

    // m-major coalesced stores
    #pragma unroll
    for (int n = 0; n < 2; ++n) {
        float* oq = g_q + (size_t)(node0 + n) * QK_STRIDE + 2 * lane;
        float* ok = g_k + (size_t)(node0 + n) * QK_STRIDE + 2 * lane;
        #pragma unroll
        for (int m = 0; m < 8; ++m) {
            *(float2*)(oq + m * 64) = make_float2(
                __uint_as_float((uint32_t)aq[n][m]),
                __uint_as_float((uint32_t)(aq[n][m] >> 32)));
            *(float2*)(ok + m * 64) = make_float2(
                __uint_as_float((uint32_t)ak[n][m]),
                __uint_as_float((uint32_t)(ak[n][m] >> 32)));
        }
    }
}

// ------------------------------------------------------------------ kernel 1: warp-specialized persistent main (1024 thr)
__global__ void __launch_bounds__(1024, 1) main_kernel(
    const float* __restrict__ t_ij, const int* __restrict__ nidx,
    const float* __restrict__ lnw, float* __restrict__ out)
{
    extern __shared__ char smem[];
    const uint32_t sb = smem_u32(smem);
    const int tid = threadIdx.x, lane = tid & 31, wid = tid >> 5;

    // ---- stage weight images ONCE (64 KB)
    {
        const char* gsrc = (const char*)g_wtiles;
        #pragma unroll
        for (int i = 0; i < 4; ++i) {
            uint32_t off = (uint32_t)(i * 16384 + tid * 16);
            CP_ASYNC16(sb + SW_E + off, gsrc + off);
        }
        CP_COMMIT();
    }
    const float gl0 = __ldg(lnw + 2 * lane), gl1 = __ldg(lnw + 2 * lane + 1);
    const float gl2 = __ldg(lnw + 64 + 2 * lane), gl3 = __ldg(lnw + 65 + 2 * lane);
    CP_WAIT0();
    __syncthreads();

    // GEMM-warp constants (wid < 16): wq = M quad, nq = N quarter
    const int wq = wid & 3;
    const int nq = (wid >> 2) & 3;
    const uint32_t a_lane = (uint32_t)((((lane >> 3) & 1) << 11) + ((lane >> 4) << 7) + ((lane & 7) << 4));
    const uint32_t b_lane = (uint32_t)(((lane >> 4) << 11) + (((lane >> 3) & 1) << 7) + ((lane & 7) << 4));
    const int r0  = wq * 32 + (lane >> 2);
    const int cbx = (lane & 3) * 2;

    const int nloc = (blockIdx.x < NT_TOTAL) ? ((NT_TOTAL - 1 - (int)blockIdx.x) / (int)gridDim.x + 1) : 0;

    for (int i = 0; i <= nloc; ++i) {
        if (wid >= 16) {
            // ================= LN warps: produce W[i&1] for tile(i), rows (wid-16)*8 .. +7
            if (i < nloc) {
                const int tile = blockIdx.x + i * (int)gridDim.x;
                const int batch = tile >> 10;
                char* wbp = smem + ((i & 1) ? SW_W1 : SW_W0);
                const int m0 = (wid - 16) * 8;
                const int node = tile * 4 + (m0 >> 5);

                const float* qp = g_q + (size_t)node * 512 + 2 * lane;
                float2 q[8];
                #pragma unroll
                for (int m = 0; m < 8; ++m) q[m] = __ldg((const float2*)(qp + m * 64));

                const int* ixp = nidx + tile * 128 + m0;
                const float* kbase = g_k + (size_t)batch * 4096 * 512 + 2 * lane;

                float2 kn[8];
                {
                    const float* kp = kbase + (size_t)__ldg(ixp) * 512;
                    #pragma unroll
                    for (int m = 0; m < 8; ++m) kn[m] = __ldg((const float2*)(kp + m * 64));
                }
                #pragma unroll
                for (int rr = 0; rr < 8; ++rr) {
                    float2 kc[8];
                    #pragma unroll
                    for (int m = 0; m < 8; ++m) kc[m] = kn[m];
                    if (rr < 7) {
                        const float* kp = kbase + (size_t)__ldg(ixp + rr + 1) * 512;
                        #pragma unroll
                        for (int m = 0; m < 8; ++m) kn[m] = __ldg((const float2*)(kp + m * 64));
                    }
                    float v0 = q[0].x*kc[0].x + q[1].x*kc[1].x + q[2].x*kc[2].x;
                    float v1 = q[0].y*kc[0].y + q[1].y*kc[1].y + q[2].y*kc[2].y;
                    float v2 = q[3].x*kc[3].x + q[4].x*kc[4].x + q[5].x*kc[5].x + q[6].x*kc[6].x + q[7].x*kc[7].x;
                    float v3 = q[3].y*kc[3].y + q[4].y*kc[4].y + q[5].y*kc[5].y + q[6].y*kc[6].y + q[7].y*kc[7].y;
                    float s  = v0 + v1 + v2 + v3;
                    float ss = v0*v0 + v1*v1 + v2*v2 + v3*v3;
                    #pragma unroll
                    for (int o = 16; o > 0; o >>= 1) {
                        s  += __shfl_xor_sync(0xffffffffu, s,  o);
                        ss += __shfl_xor_sync(0xffffffffu, ss, o);
                    }
                    const float mu = s * (1.f / 128.f);
                    const float var = ss * (1.f / 128.f) - mu * mu;
                    const float sc = rsqrtf(fmaxf(var, 0.f) + 1e-5f);
                    v0 = (v0 - mu) * sc * gl0; v1 = (v1 - mu) * sc * gl1;
                    v2 = (v2 - mu) * sc * gl2; v3 = (v3 - mu) * sc * gl3;
                    const int m = m0 + rr;
                    const uint32_t off1 = (uint32_t)(((m >> 3) << 11) + ((m & 7) << 4)
                                                     + ((lane >> 2) << 7) + ((lane & 3) << 2));
                    *(uint32_t*)(wbp + off1)         = pack_f16x2(v0, v1);
                    *(uint32_t*)(wbp + off1 + 1024u) = pack_f16x2(v2, v3);
                }
            }
        } else if (i >= 1) {
            // ================= GEMM warps: consume W[(i-1)&1] for tile(i-1)
            // acc = sigmoid(W @ E) computed first, then T @ R accumulated on top.
            const int tile = blockIdx.x + (i - 1) * (int)gridDim.x;
            const uint32_t wb = sb + (((i - 1) & 1) ? SW_W1 : SW_W0);
            const float* tb = t_ij + (size_t)tile * 16384;
            float* ob = out + (size_t)tile * 16384;

            float acc[32];
            #pragma unroll
            for (int z = 0; z < 32; ++z) acc[z] = 0.f;

            // ---- edge GEMM: fp16 (A = normalized W from smem)
            #pragma unroll
            for (int ks = 0; ks < 8; ++ks) {
                uint32_t ah[8];
                const uint32_t aoff = a_lane + (uint32_t)(ks * 256);
                LDSM_X4(ah[0], ah[1], ah[2], ah[3], wb + (uint32_t)((4 * wq) * 2048) + aoff);
                LDSM_X4(ah[4], ah[5], ah[6], ah[7], wb + (uint32_t)((4 * wq + 2) * 2048) + aoff);
                #pragma unroll
                for (int ntp = 0; ntp < 2; ++ntp) {
                    const uint32_t boff = (uint32_t)((nq * 4 + ntp * 2) << 11) + b_lane + (uint32_t)(ks << 8);
                    uint32_t e0, e1, e2, e3;
                    LDSM_X4(e0, e1, e2, e3, sb + SW_E + boff);
                    MMA_F16(&acc[((0 * 2 + ntp) * 2 + 0) * 4], ah[0], ah[1], ah[2], ah[3], e0, e1);
                    MMA_F16(&acc[((0 * 2 + ntp) * 2 + 1) * 4], ah[0], ah[1], ah[2], ah[3], e2, e3);
                    MMA_F16(&acc[((1 * 2 + ntp) * 2 + 0) * 4], ah[4], ah[5], ah[6], ah[7], e0, e1);
                    MMA_F16(&acc[((1 * 2 + ntp) * 2 + 1) * 4], ah[4], ah[5], ah[6], ah[7], e2, e3);
                }
            }
            // ---- sigmoid in place
            #pragma unroll
            for (int z = 0; z < 32; ++z) acc[z] = 1.f / (1.f + __expf(-acc[z]));

            // ---- res GEMM: fp16, accumulates onto sigmoid values
            #pragma unroll
            for (int ks = 0; ks < 8; ++ks) {
                uint32_t th[8];
                const int col = ks * 16 + cbx;
                #pragma unroll
                for (int mi = 0; mi < 2; ++mi) {
                    const int rr = r0 + mi * 16;
                    float2 v0 = __ldg((const float2*)(tb + rr * 128 + col));
                    float2 v1 = __ldg((const float2*)(tb + (rr + 8) * 128 + col));
                    float2 v2 = __ldg((const float2*)(tb + rr * 128 + col + 8));
                    float2 v3 = __ldg((const float2*)(tb + (rr + 8) * 128 + col + 8));
                    th[mi * 4 + 0] = pack_f16x2(v0.x, v0.y);
                    th[mi * 4 + 1] = pack_f16x2(v1.x, v1.y);
                    th[mi * 4 + 2] = pack_f16x2(v2.x, v2.y);
                    th[mi * 4 + 3] = pack_f16x2(v3.x, v3.y);
                }
                #pragma unroll
                for (int ntp = 0; ntp < 2; ++ntp) {
                    const uint32_t boff = (uint32_t)((nq * 4 + ntp * 2) << 11) + b_lane + (uint32_t)(ks << 8);
                    uint32_t b0, b1, b2, b3;
                    LDSM_X4(b0, b1, b2, b3, sb + SW_R + boff);
                    MMA_F16(&acc[((0 * 2 + ntp) * 2 + 0) * 4], th[0], th[1], th[2], th[3], b0, b1);
                    MMA_F16(&acc[((0 * 2 + ntp) * 2 + 1) * 4], th[0], th[1], th[2], th[3], b2, b3);
                    MMA_F16(&acc[((1 * 2 + ntp) * 2 + 0) * 4], th[4], th[5], th[6], th[7], b0, b1);
                    MMA_F16(&acc[((1 * 2 + ntp) * 2 + 1) * 4], th[4], th[5], th[6], th[7], b2, b3);
                }
            }
            // ---- store (values already final)
            #pragma unroll
            for (int mi = 0; mi < 2; ++mi) {
                #pragma unroll
                for (int ntp = 0; ntp < 2; ++ntp) {
                    #pragma unroll
                    for (int sub = 0; sub < 2; ++sub) {
                        const int g4 = ((mi * 2 + ntp) * 2 + sub) * 4;
                        const int rr = r0 + mi * 16;
                        const int col = nq * 32 + ntp * 16 + sub * 8 + cbx;
                        *(float2*)(ob + rr * 128 + col)       = make_float2(acc[g4 + 0], acc[g4 + 1]);
                        *(float2*)(ob + (rr + 8) * 128 + col) = make_float2(acc[g4 + 2], acc[g4 + 3]);
                    }
                }
            }
        }
        __syncthreads();   // pipeline step: swap W buffers
    }
}

// ------------------------------------------------------------------ launch
extern "C" void kernel_launch(void* const* d_in, const int* in_sizes, int n_in,
                              void* d_out, int out_size)
{
    const float* t_ij = (const float*)d_in[0];
    const float* x1   = (const float*)d_in[1];
    const float* x2   = (const float*)d_in[2];
    const int*   nidx = (const int*)  d_in[3];
    const float* tq   = (const float*)d_in[4];
    const float* tk1  = (const float*)d_in[5];
    const float* tk2  = (const float*)d_in[6];
    const float* lnw  = (const float*)d_in[7];
    const float* ew   = (const float*)d_in[8];
    const float* rw   = (const float*)d_in[9];
    float* out = (float*)d_out;

    int dev = 0, nsm = 148;
    cudaGetDevice(&dev);
    cudaDeviceGetAttribute(&nsm, cudaDevAttrMultiProcessorCount, dev);

    cudaFuncSetAttribute(prep_kernel, cudaFuncAttributeMaxDynamicSharedMemorySize, PREP_SMEM);
    cudaFuncSetAttribute(main_kernel, cudaFuncAttributeMaxDynamicSharedMemorySize, SMEM_B);

    prep_kernel<<<64 + NNODES / 32, 512, PREP_SMEM>>>(ew, rw, x1, x2, tq, tk1, tk2);
    main_kernel<<<nsm, 1024, SMEM_B>>>(t_ij, nidx, lnw, out);
}

// round 15
// speedup vs baseline: 1.2023x; 1.1073x over previous
#include <cuda_runtime.h>
#include <cuda_bf16.h>
#include <cstdint>

#define NNODES 8192
#define QK_STRIDE 512
#define NT_TOTAL 2048        // 4 nodes per tile (M=128)

// ------------------------------------------------------------------ scratch
// m-major layout: g_q/g_k[node*512 + m*64 + e], m in [0,8), e in [0,64)
__device__ __align__(16) float g_q[(size_t)NNODES * QK_STRIDE];
__device__ __align__(16) float g_k[(size_t)NNODES * QK_STRIDE];
// 2 tile-blocked fp16 weight images, 32KB each: [E][R]
__device__ __align__(16) unsigned char g_wtiles[2 * 32768];
// 3 tile-blocked fp16 projection-weight images, 16KB each: [tq][tk1][tk2]  (n=e<64, k=d<128)
__device__ __align__(16) unsigned char g_ptiles[3 * 16384];

// ------------------------------------------------------------------ helpers
__device__ __forceinline__ uint32_t smem_u32(const void* p) {
    uint32_t a;
    asm("{ .reg .u64 t; cvta.to.shared.u64 t, %1; cvt.u32.u64 %0, t; }" : "=r"(a) : "l"(p));
    return a;
}
__device__ __forceinline__ uint32_t pack_f16x2(float a, float b) {   // lo=f16(a), hi=f16(b)
    uint32_t p;
    asm("cvt.rn.f16x2.f32 %0, %1, %2;" : "=r"(p) : "f"(b), "f"(a));
    return p;
}
#define LDSM_X4(r0, r1, r2, r3, addr) \
    asm volatile("ldmatrix.sync.aligned.m8n8.x4.shared.b16 {%0,%1,%2,%3}, [%4];" \
        : "=r"(r0), "=r"(r1), "=r"(r2), "=r"(r3) : "r"(addr))
#define MMA_F16(c, a0, a1, a2, a3, b0, b1) \
    asm volatile("mma.sync.aligned.m16n8k16.row.col.f32.f16.f16.f32 " \
        "{%0,%1,%2,%3}, {%4,%5,%6,%7}, {%8,%9}, {%0,%1,%2,%3};" \
        : "+f"((c)[0]), "+f"((c)[1]), "+f"((c)[2]), "+f"((c)[3]) \
        : "r"(a0), "r"(a1), "r"(a2), "r"(a3), "r"(b0), "r"(b1))
#define CP_ASYNC16(saddr, gptr) \
    asm volatile("cp.async.cg.shared.global [%0], [%1], 16;" :: "r"(saddr), "l"(gptr))
#define CP_COMMIT() asm volatile("cp.async.commit_group;")
#define CP_WAIT0()  asm volatile("cp.async.wait_group 0;" ::: "memory")

// ------------------------------------------------------------------ main smem map (bytes)
#define SW_E   0          // 32768 fp16 edge image
#define SW_R   32768      // 32768 fp16 res image
#define SW_W0  65536      // 32768 fp16 W buf 0 (M=128)
#define SW_W1  98304      // 32768 fp16 W buf 1
#define SMEM_B 131072

// proj smem map (bytes)
#define PB_Q   0          // 16384
#define PB_K1  16384      // 16384
#define PB_K2  32768      // 16384
#define PA     49152      // 32768 fp16 A tile (128 rows x 128 k)
#define PROJ_SMEM 81920

// ------------------------------------------------------------------ kernel 0: weight conversion
__global__ void __launch_bounds__(512) wconv_kernel(
    const float* __restrict__ ew,  const float* __restrict__ rw,
    const float* __restrict__ tq,  const float* __restrict__ tk1,
    const float* __restrict__ tk2)
{
    const int tid = threadIdx.x;
    if (blockIdx.x < 64) {
        // ---- edge/res GEMM B images (fp16), n<128, k<128
        int id = blockIdx.x * 512 + tid;              // 0..32767
        int w = id >> 14, k = (id >> 7) & 127, n = id & 127;
        float v = (w ? rw : ew)[k * 128 + n];         // B[n][k] = W[k][n]
        uint32_t off = (uint32_t)(((n >> 3) * 8 + (k >> 4)) * 256 + (((k >> 3) & 1) << 7)
                                  + ((n & 7) << 4) + ((k & 7) << 1));
        uint32_t p = pack_f16x2(v, 0.f);
        *(uint16_t*)(g_wtiles + (size_t)w * 32768 + off) = (uint16_t)(p & 0xffffu);
    } else {
        // ---- projection weight images (fp16), n=e<64, k=d<128
        int idx = (blockIdx.x - 64) * 512 + tid;      // 0..24575
        int w = idx >> 13;                             // 0=tq 1=tk1 2=tk2
        int rem = idx & 8191;
        int k = rem >> 6, n = rem & 63;
        const float* src = (w == 0) ? tq : (w == 1) ? tk1 : tk2;
        float v = src[k * 64 + n];                     // B[n][k] = W[k][n]
        uint32_t off = (uint32_t)(((n >> 3) * 8 + (k >> 4)) * 256 + (((k >> 3) & 1) << 7)
                                  + ((n & 7) << 4) + ((k & 7) << 1));
        uint32_t p = pack_f16x2(v, 0.f);
        *(uint16_t*)(g_ptiles + (size_t)w * 16384 + off) = (uint16_t)(p & 0xffffu);
    }
}

// ------------------------------------------------------------------ kernel 1: projections via tensor cores
// Per block: 16 nodes (M = 128 rows = node_local*8 + m), 3 GEMMs vs tq/tk1/tk2.
__global__ void __launch_bounds__(256) proj_kernel(
    const float* __restrict__ x1, const float* __restrict__ x2)
{
    extern __shared__ char smem[];
    const uint32_t sb = smem_u32(smem);
    const int tid = threadIdx.x, lane = tid & 31, wid = tid >> 5;
    const int tile = blockIdx.x;
    const int node0 = tile * 16;

    // ---- stage B images (48 KB) via cp.async
    #pragma unroll
    for (int i = 0; i < 12; ++i) {
        uint32_t off = (uint32_t)(i * 4096 + tid * 16);
        CP_ASYNC16(sb + off, (const char*)g_ptiles + off);
    }
    CP_COMMIT();

    // ---- stage A: x -> fp16 blocked layout
    #pragma unroll 8
    for (int idx = tid; idx < 16384; idx += 256) {
        const int r = idx >> 7, d = idx & 127;
        const int m = r & 7, nl = r >> 3;
        float v = (m < 3)
            ? __ldg(x1 + (size_t)(node0 + nl) * 384 + d * 3 + m)
            : __ldg(x2 + (size_t)(node0 + nl) * 640 + d * 5 + (m - 3));
        const uint32_t ao = (uint32_t)(((r >> 3) * 16 + (d >> 3)) * 128 + ((r & 7) << 4) + ((d & 7) << 1));
        *(uint16_t*)(smem + PA + ao) = (uint16_t)(pack_f16x2(v, 0.f) & 0xffffu);
    }
    CP_WAIT0();
    __syncthreads();

    // ---- 3 GEMMs: Q = A*tq, K1 = A*tk1, K2 = A*tk2
    const int wq = wid & 3;           // M quad (32 rows)
    const int nqh = wid >> 2;         // N half (32 cols)
    const uint32_t a_lane = (uint32_t)((((lane >> 3) & 1) << 11) + ((lane >> 4) << 7) + ((lane & 7) << 4));
    const uint32_t b_lane = (uint32_t)(((lane >> 4) << 11) + (((lane >> 3) & 1) << 7) + ((lane & 7) << 4));
    const int r0  = wq * 32 + (lane >> 2);
    const int cbx = (lane & 3) * 2;

    float aQ[32], aK1[32], aK2[32];
    #pragma unroll
    for (int z = 0; z < 32; ++z) { aQ[z] = 0.f; aK1[z] = 0.f; aK2[z] = 0.f; }

    #pragma unroll
    for (int ks = 0; ks < 8; ++ks) {
        uint32_t ah[8];
        const uint32_t aoff = a_lane + (uint32_t)(ks * 256);
        LDSM_X4(ah[0], ah[1], ah[2], ah[3], sb + PA + (uint32_t)((4 * wq) * 2048) + aoff);
        LDSM_X4(ah[4], ah[5], ah[6], ah[7], sb + PA + (uint32_t)((4 * wq + 2) * 2048) + aoff);
        #pragma unroll
        for (int ntp = 0; ntp < 2; ++ntp) {
            const uint32_t boff = (uint32_t)((nqh * 4 + ntp * 2) << 11) + b_lane + (uint32_t)(ks << 8);
            uint32_t b0, b1, b2, b3;
            LDSM_X4(b0, b1, b2, b3, sb + PB_Q + boff);
            MMA_F16(&aQ[((0 * 2 + ntp) * 2 + 0) * 4], ah[0], ah[1], ah[2], ah[3], b0, b1);
            MMA_F16(&aQ[((0 * 2 + ntp) * 2 + 1) * 4], ah[0], ah[1], ah[2], ah[3], b2, b3);
            MMA_F16(&aQ[((1 * 2 + ntp) * 2 + 0) * 4], ah[4], ah[5], ah[6], ah[7], b0, b1);
            MMA_F16(&aQ[((1 * 2 + ntp) * 2 + 1) * 4], ah[4], ah[5], ah[6], ah[7], b2, b3);
            LDSM_X4(b0, b1, b2, b3, sb + PB_K1 + boff);
            MMA_F16(&aK1[((0 * 2 + ntp) * 2 + 0) * 4], ah[0], ah[1], ah[2], ah[3], b0, b1);
            MMA_F16(&aK1[((0 * 2 + ntp) * 2 + 1) * 4], ah[0], ah[1], ah[2], ah[3], b2, b3);
            MMA_F16(&aK1[((1 * 2 + ntp) * 2 + 0) * 4], ah[4], ah[5], ah[6], ah[7], b0, b1);
            MMA_F16(&aK1[((1 * 2 + ntp) * 2 + 1) * 4], ah[4], ah[5], ah[6], ah[7], b2, b3);
            LDSM_X4(b0, b1, b2, b3, sb + PB_K2 + boff);
            MMA_F16(&aK2[((0 * 2 + ntp) * 2 + 0) * 4], ah[0], ah[1], ah[2], ah[3], b0, b1);
            MMA_F16(&aK2[((0 * 2 + ntp) * 2 + 1) * 4], ah[0], ah[1], ah[2], ah[3], b2, b3);
            MMA_F16(&aK2[((1 * 2 + ntp) * 2 + 0) * 4], ah[4], ah[5], ah[6], ah[7], b0, b1);
            MMA_F16(&aK2[((1 * 2 + ntp) * 2 + 1) * 4], ah[4], ah[5], ah[6], ah[7], b2, b3);
        }
    }

    // ---- stores: q always; k selects tk1-result (m<3) or tk2-result (m>=3)
    // every fragment row of this lane has the same m = lane>>2
    const bool k1sel = ((lane >> 2) < 3);
    const int m = lane >> 2;
    #pragma unroll
    for (int mi = 0; mi < 2; ++mi) {
        #pragma unroll
        for (int ntp = 0; ntp < 2; ++ntp) {
            #pragma unroll
            for (int sub = 0; sub < 2; ++sub) {
                const int g4 = ((mi * 2 + ntp) * 2 + sub) * 4;
                const int rr = r0 + mi * 16;
                const int col = nqh * 32 + ntp * 16 + sub * 8 + cbx;
                const int nodeA = node0 + (rr >> 3);
                const int nodeB = node0 + ((rr + 8) >> 3);
                *(float2*)(g_q + (size_t)nodeA * 512 + m * 64 + col) = make_float2(aQ[g4 + 0], aQ[g4 + 1]);
                *(float2*)(g_q + (size_t)nodeB * 512 + m * 64 + col) = make_float2(aQ[g4 + 2], aQ[g4 + 3]);
                const float k0 = k1sel ? aK1[g4 + 0] : aK2[g4 + 0];
                const float k1 = k1sel ? aK1[g4 + 1] : aK2[g4 + 1];
                const float k2 = k1sel ? aK1[g4 + 2] : aK2[g4 + 2];
                const float k3 = k1sel ? aK1[g4 + 3] : aK2[g4 + 3];
                *(float2*)(g_k + (size_t)nodeA * 512 + m * 64 + col) = make_float2(k0, k1);
                *(float2*)(g_k + (size_t)nodeB * 512 + m * 64 + col) = make_float2(k2, k3);
            }
        }
    }
}

// ------------------------------------------------------------------ kernel 2: warp-specialized persistent main (1024 thr)
__global__ void __launch_bounds__(1024, 1) main_kernel(
    const float* __restrict__ t_ij, const int* __restrict__ nidx,
    const float* __restrict__ lnw, float* __restrict__ out)
{
    extern __shared__ char smem[];
    const uint32_t sb = smem_u32(smem);
    const int tid = threadIdx.x, lane = tid & 31, wid = tid >> 5;

    // ---- stage weight images ONCE (64 KB)
    {
        const char* gsrc = (const char*)g_wtiles;
        #pragma unroll
        for (int i = 0; i < 4; ++i) {
            uint32_t off = (uint32_t)(i * 16384 + tid * 16);
            CP_ASYNC16(sb + SW_E + off, gsrc + off);
        }
        CP_COMMIT();
    }
    const float gl0 = __ldg(lnw + 2 * lane), gl1 = __ldg(lnw + 2 * lane + 1);
    const float gl2 = __ldg(lnw + 64 + 2 * lane), gl3 = __ldg(lnw + 65 + 2 * lane);
    CP_WAIT0();
    __syncthreads();

    // GEMM-warp constants (wid < 16): wq = M quad, nq = N quarter
    const int wq = wid & 3;
    const int nq = (wid >> 2) & 3;
    const uint32_t a_lane = (uint32_t)((((lane >> 3) & 1) << 11) + ((lane >> 4) << 7) + ((lane & 7) << 4));
    const uint32_t b_lane = (uint32_t)(((lane >> 4) << 11) + (((lane >> 3) & 1) << 7) + ((lane & 7) << 4));
    const int r0  = wq * 32 + (lane >> 2);
    const int cbx = (lane & 3) * 2;

    const int nloc = (blockIdx.x < NT_TOTAL) ? ((NT_TOTAL - 1 - (int)blockIdx.x) / (int)gridDim.x + 1) : 0;

    for (int i = 0; i <= nloc; ++i) {
        if (wid >= 16) {
            // ================= LN warps: produce W[i&1] for tile(i), rows (wid-16)*8 .. +7
            if (i < nloc) {
                const int tile = blockIdx.x + i * (int)gridDim.x;
                const int batch = tile >> 10;
                char* wbp = smem + ((i & 1) ? SW_W1 : SW_W0);
                const int m0 = (wid - 16) * 8;
                const int node = tile * 4 + (m0 >> 5);

                const float* qp = g_q + (size_t)node * 512 + 2 * lane;
                float2 q[8];
                #pragma unroll
                for (int m = 0; m < 8; ++m) q[m] = __ldg((const float2*)(qp + m * 64));

                const int* ixp = nidx + tile * 128 + m0;
                const float* kbase = g_k + (size_t)batch * 4096 * 512 + 2 * lane;

                float2 kn[8];
                {
                    const float* kp = kbase + (size_t)__ldg(ixp) * 512;
                    #pragma unroll
                    for (int m = 0; m < 8; ++m) kn[m] = __ldg((const float2*)(kp + m * 64));
                }
                #pragma unroll
                for (int rr = 0; rr < 8; ++rr) {
                    float2 kc[8];
                    #pragma unroll
                    for (int m = 0; m < 8; ++m) kc[m] = kn[m];
                    if (rr < 7) {
                        const float* kp = kbase + (size_t)__ldg(ixp + rr + 1) * 512;
                        #pragma unroll
                        for (int m = 0; m < 8; ++m) kn[m] = __ldg((const float2*)(kp + m * 64));
                    }
                    float v0 = q[0].x*kc[0].x + q[1].x*kc[1].x + q[2].x*kc[2].x;
                    float v1 = q[0].y*kc[0].y + q[1].y*kc[1].y + q[2].y*kc[2].y;
                    float v2 = q[3].x*kc[3].x + q[4].x*kc[4].x + q[5].x*kc[5].x + q[6].x*kc[6].x + q[7].x*kc[7].x;
                    float v3 = q[3].y*kc[3].y + q[4].y*kc[4].y + q[5].y*kc[5].y + q[6].y*kc[6].y + q[7].y*kc[7].y;
                    float s  = v0 + v1 + v2 + v3;
                    float ss = v0*v0 + v1*v1 + v2*v2 + v3*v3;
                    #pragma unroll
                    for (int o = 16; o > 0; o >>= 1) {
                        s  += __shfl_xor_sync(0xffffffffu, s,  o);
                        ss += __shfl_xor_sync(0xffffffffu, ss, o);
                    }
                    const float mu = s * (1.f / 128.f);
                    const float var = ss * (1.f / 128.f) - mu * mu;
                    const float sc = rsqrtf(fmaxf(var, 0.f) + 1e-5f);
                    v0 = (v0 - mu) * sc * gl0; v1 = (v1 - mu) * sc * gl1;
                    v2 = (v2 - mu) * sc * gl2; v3 = (v3 - mu) * sc * gl3;
                    const int m = m0 + rr;
                    const uint32_t off1 = (uint32_t)(((m >> 3) << 11) + ((m & 7) << 4)
                                                     + ((lane >> 2) << 7) + ((lane & 3) << 2));
                    *(uint32_t*)(wbp + off1)         = pack_f16x2(v0, v1);
                    *(uint32_t*)(wbp + off1 + 1024u) = pack_f16x2(v2, v3);
                }
            }
        } else if (i >= 1) {
            // ================= GEMM warps: consume W[(i-1)&1] for tile(i-1)
            // acc = sigmoid(W @ E) computed first, then T @ R accumulated on top.
            const int tile = blockIdx.x + (i - 1) * (int)gridDim.x;
            const uint32_t wb = sb + (((i - 1) & 1) ? SW_W1 : SW_W0);
            const float* tb = t_ij + (size_t)tile * 16384;
            float* ob = out + (size_t)tile * 16384;

            float acc[32];
            #pragma unroll
            for (int z = 0; z < 32; ++z) acc[z] = 0.f;

            // ---- edge GEMM: fp16 (A = normalized W from smem)
            #pragma unroll
            for (int ks = 0; ks < 8; ++ks) {
                uint32_t ah[8];
                const uint32_t aoff = a_lane + (uint32_t)(ks * 256);
                LDSM_X4(ah[0], ah[1], ah[2], ah[3], wb + (uint32_t)((4 * wq) * 2048) + aoff);
                LDSM_X4(ah[4], ah[5], ah[6], ah[7], wb + (uint32_t)((4 * wq + 2) * 2048) + aoff);
                #pragma unroll
                for (int ntp = 0; ntp < 2; ++ntp) {
                    const uint32_t boff = (uint32_t)((nq * 4 + ntp * 2) << 11) + b_lane + (uint32_t)(ks << 8);
                    uint32_t e0, e1, e2, e3;
                    LDSM_X4(e0, e1, e2, e3, sb + SW_E + boff);
                    MMA_F16(&acc[((0 * 2 + ntp) * 2 + 0) * 4], ah[0], ah[1], ah[2], ah[3], e0, e1);
                    MMA_F16(&acc[((0 * 2 + ntp) * 2 + 1) * 4], ah[0], ah[1], ah[2], ah[3], e2, e3);
                    MMA_F16(&acc[((1 * 2 + ntp) * 2 + 0) * 4], ah[4], ah[5], ah[6], ah[7], e0, e1);
                    MMA_F16(&acc[((1 * 2 + ntp) * 2 + 1) * 4], ah[4], ah[5], ah[6], ah[7], e2, e3);
                }
            }
            // ---- sigmoid in place
            #pragma unroll
            for (int z = 0; z < 32; ++z) acc[z] = 1.f / (1.f + __expf(-acc[z]));

            // ---- res GEMM: fp16, accumulates onto sigmoid values
            #pragma unroll
            for (int ks = 0; ks < 8; ++ks) {
                uint32_t th[8];
                const int col = ks * 16 + cbx;
                #pragma unroll
                for (int mi = 0; mi < 2; ++mi) {
                    const int rr = r0 + mi * 16;
                    float2 v0 = __ldg((const float2*)(tb + rr * 128 + col));
                    float2 v1 = __ldg((const float2*)(tb + (rr + 8) * 128 + col));
                    float2 v2 = __ldg((const float2*)(tb + rr * 128 + col + 8));
                    float2 v3 = __ldg((const float2*)(tb + (rr + 8) * 128 + col + 8));
                    th[mi * 4 + 0] = pack_f16x2(v0.x, v0.y);
                    th[mi * 4 + 1] = pack_f16x2(v1.x, v1.y);
                    th[mi * 4 + 2] = pack_f16x2(v2.x, v2.y);
                    th[mi * 4 + 3] = pack_f16x2(v3.x, v3.y);
                }
                #pragma unroll
                for (int ntp = 0; ntp < 2; ++ntp) {
                    const uint32_t boff = (uint32_t)((nq * 4 + ntp * 2) << 11) + b_lane + (uint32_t)(ks << 8);
                    uint32_t b0, b1, b2, b3;
                    LDSM_X4(b0, b1, b2, b3, sb + SW_R + boff);
                    MMA_F16(&acc[((0 * 2 + ntp) * 2 + 0) * 4], th[0], th[1], th[2], th[3], b0, b1);
                    MMA_F16(&acc[((0 * 2 + ntp) * 2 + 1) * 4], th[0], th[1], th[2], th[3], b2, b3);
                    MMA_F16(&acc[((1 * 2 + ntp) * 2 + 0) * 4], th[4], th[5], th[6], th[7], b0, b1);
                    MMA_F16(&acc[((1 * 2 + ntp) * 2 + 1) * 4], th[4], th[5], th[6], th[7], b2, b3);
                }
            }
            // ---- store (values already final)
            #pragma unroll
            for (int mi = 0; mi < 2; ++mi) {
                #pragma unroll
                for (int ntp = 0; ntp < 2; ++ntp) {
                    #pragma unroll
                    for (int sub = 0; sub < 2; ++sub) {
                        const int g4 = ((mi * 2 + ntp) * 2 + sub) * 4;
                        const int rr = r0 + mi * 16;
                        const int col = nq * 32 + ntp * 16 + sub * 8 + cbx;
                        *(float2*)(ob + rr * 128 + col)       = make_float2(acc[g4 + 0], acc[g4 + 1]);
                        *(float2*)(ob + (rr + 8) * 128 + col) = make_float2(acc[g4 + 2], acc[g4 + 3]);
                    }
                }
            }
        }
        __syncthreads();   // pipeline step: swap W buffers
    }
}

// ------------------------------------------------------------------ launch
extern "C" void kernel_launch(void* const* d_in, const int* in_sizes, int n_in,
                              void* d_out, int out_size)
{
    const float* t_ij = (const float*)d_in[0];
    const float* x1   = (const float*)d_in[1];
    const float* x2   = (const float*)d_in[2];
    const int*   nidx = (const int*)  d_in[3];
    const float* tq   = (const float*)d_in[4];
    const float* tk1  = (const float*)d_in[5];
    const float* tk2  = (const float*)d_in[6];
    const float* lnw  = (const float*)d_in[7];
    const float* ew   = (const float*)d_in[8];
    const float* rw   = (const float*)d_in[9];
    float* out = (float*)d_out;

    int dev = 0, nsm = 148;
    cudaGetDevice(&dev);
    cudaDeviceGetAttribute(&nsm, cudaDevAttrMultiProcessorCount, dev);

    cudaFuncSetAttribute(proj_kernel, cudaFuncAttributeMaxDynamicSharedMemorySize, PROJ_SMEM);
    cudaFuncSetAttribute(main_kernel, cudaFuncAttributeMaxDynamicSharedMemorySize, SMEM_B);

    wconv_kernel<<<112, 512>>>(ew, rw, tq, tk1, tk2);
    proj_kernel<<<NNODES / 16, 256, PROJ_SMEM>>>(x1, x2);
    main_kernel<<<nsm, 1024, SMEM_B>>>(t_ij, nidx, lnw, out);
}

// round 16
// speedup vs baseline: 1.3913x; 1.1571x over previous
#include <cuda_runtime.h>
#include <cuda_bf16.h>
#include <cuda_fp16.h>
#include <cstdint>

#define NNODES 8192
#define QK_STRIDE 512
#define NT_TOTAL 2048        // 4 nodes per tile (M=128)

// ------------------------------------------------------------------ scratch
// m-major layout: [node*512 + m*64 + e], m in [0,8), e in [0,64)
__device__ __align__(16) float    g_q[(size_t)NNODES * QK_STRIDE];   // fp32
__device__ __align__(16) uint16_t g_k[(size_t)NNODES * QK_STRIDE];   // fp16
// 2 tile-blocked fp16 weight images, 32KB each: [E][R]
__device__ __align__(16) unsigned char g_wtiles[2 * 32768];
// 3 tile-blocked fp16 projection-weight images, 16KB each: [tq][tk1][tk2]
__device__ __align__(16) unsigned char g_ptiles[3 * 16384];

// ------------------------------------------------------------------ helpers
__device__ __forceinline__ uint32_t smem_u32(const void* p) {
    uint32_t a;
    asm("{ .reg .u64 t; cvta.to.shared.u64 t, %1; cvt.u32.u64 %0, t; }" : "=r"(a) : "l"(p));
    return a;
}
__device__ __forceinline__ uint32_t pack_f16x2(float a, float b) {   // lo=f16(a), hi=f16(b)
    uint32_t p;
    asm("cvt.rn.f16x2.f32 %0, %1, %2;" : "=r"(p) : "f"(b), "f"(a));
    return p;
}
__device__ __forceinline__ float2 h2f2(uint32_t h) {
    return __half22float2(*reinterpret_cast<const __half2*>(&h));
}
#define LDSM_X4(r0, r1, r2, r3, addr) \
    asm volatile("ldmatrix.sync.aligned.m8n8.x4.shared.b16 {%0,%1,%2,%3}, [%4];" \
        : "=r"(r0), "=r"(r1), "=r"(r2), "=r"(r3) : "r"(addr))
#define MMA_F16(c, a0, a1, a2, a3, b0, b1) \
    asm volatile("mma.sync.aligned.m16n8k16.row.col.f32.f16.f16.f32 " \
        "{%0,%1,%2,%3}, {%4,%5,%6,%7}, {%8,%9}, {%0,%1,%2,%3};" \
        : "+f"((c)[0]), "+f"((c)[1]), "+f"((c)[2]), "+f"((c)[3]) \
        : "r"(a0), "r"(a1), "r"(a2), "r"(a3), "r"(b0), "r"(b1))
#define CP_ASYNC16(saddr, gptr) \
    asm volatile("cp.async.cg.shared.global [%0], [%1], 16;" :: "r"(saddr), "l"(gptr))
#define CP_COMMIT() asm volatile("cp.async.commit_group;")
#define CP_WAIT0()  asm volatile("cp.async.wait_group 0;" ::: "memory")
#define GEMM_BAR()  asm volatile("bar.sync 2, 512;" ::: "memory")

// ------------------------------------------------------------------ main smem map (bytes)
#define SW_E   0          // 32768 fp16 edge image
#define SW_R   32768      // 32768 fp16 res image
#define SW_W0  65536      // 32768 fp16 W buf 0 (M=128)
#define SW_W1  98304      // 32768 fp16 W buf 1
#define SW_T   131072     // 32768 fp16 T tile (blocked)
#define SMEM_B 163840

// proj smem map (bytes)
#define PB_Q   0
#define PB_K1  16384
#define PB_K2  32768
#define PA     49152
#define PROJ_SMEM 81920

// ------------------------------------------------------------------ kernel 0: weight conversion
__global__ void __launch_bounds__(512) wconv_kernel(
    const float* __restrict__ ew,  const float* __restrict__ rw,
    const float* __restrict__ tq,  const float* __restrict__ tk1,
    const float* __restrict__ tk2)
{
    const int tid = threadIdx.x;
    if (blockIdx.x < 64) {
        int id = blockIdx.x * 512 + tid;
        int w = id >> 14, k = (id >> 7) & 127, n = id & 127;
        float v = (w ? rw : ew)[k * 128 + n];
        uint32_t off = (uint32_t)(((n >> 3) * 8 + (k >> 4)) * 256 + (((k >> 3) & 1) << 7)
                                  + ((n & 7) << 4) + ((k & 7) << 1));
        *(uint16_t*)(g_wtiles + (size_t)w * 32768 + off) = (uint16_t)(pack_f16x2(v, 0.f) & 0xffffu);
    } else {
        int idx = (blockIdx.x - 64) * 512 + tid;      // 0..24575
        int w = idx >> 13;
        int rem = idx & 8191;
        int k = rem >> 6, n = rem & 63;
        const float* src = (w == 0) ? tq : (w == 1) ? tk1 : tk2;
        float v = src[k * 64 + n];
        uint32_t off = (uint32_t)(((n >> 3) * 8 + (k >> 4)) * 256 + (((k >> 3) & 1) << 7)
                                  + ((n & 7) << 4) + ((k & 7) << 1));
        *(uint16_t*)(g_ptiles + (size_t)w * 16384 + off) = (uint16_t)(pack_f16x2(v, 0.f) & 0xffffu);
    }
}

// ------------------------------------------------------------------ kernel 1: projections via tensor cores
__global__ void __launch_bounds__(256) proj_kernel(
    const float* __restrict__ x1, const float* __restrict__ x2)
{
    extern __shared__ char smem[];
    const uint32_t sb = smem_u32(smem);
    const int tid = threadIdx.x, lane = tid & 31, wid = tid >> 5;
    const int node0 = blockIdx.x * 16;

    #pragma unroll
    for (int i = 0; i < 12; ++i) {
        uint32_t off = (uint32_t)(i * 4096 + tid * 16);
        CP_ASYNC16(sb + off, (const char*)g_ptiles + off);
    }
    CP_COMMIT();

    #pragma unroll 8
    for (int idx = tid; idx < 16384; idx += 256) {
        const int r = idx >> 7, d = idx & 127;
        const int m = r & 7, nl = r >> 3;
        float v = (m < 3)
            ? __ldg(x1 + (size_t)(node0 + nl) * 384 + d * 3 + m)
            : __ldg(x2 + (size_t)(node0 + nl) * 640 + d * 5 + (m - 3));
        const uint32_t ao = (uint32_t)(((r >> 3) * 16 + (d >> 3)) * 128 + ((r & 7) << 4) + ((d & 7) << 1));
        *(uint16_t*)(smem + PA + ao) = (uint16_t)(pack_f16x2(v, 0.f) & 0xffffu);
    }
    CP_WAIT0();
    __syncthreads();

    const int wq = wid & 3;
    const int nqh = wid >> 2;
    const uint32_t a_lane = (uint32_t)((((lane >> 3) & 1) << 11) + ((lane >> 4) << 7) + ((lane & 7) << 4));
    const uint32_t b_lane = (uint32_t)(((lane >> 4) << 11) + (((lane >> 3) & 1) << 7) + ((lane & 7) << 4));
    const int r0  = wq * 32 + (lane >> 2);
    const int cbx = (lane & 3) * 2;

    float aQ[32], aK1[32], aK2[32];
    #pragma unroll
    for (int z = 0; z < 32; ++z) { aQ[z] = 0.f; aK1[z] = 0.f; aK2[z] = 0.f; }

    #pragma unroll
    for (int ks = 0; ks < 8; ++ks) {
        uint32_t ah[8];
        const uint32_t aoff = a_lane + (uint32_t)(ks * 256);
        LDSM_X4(ah[0], ah[1], ah[2], ah[3], sb + PA + (uint32_t)((4 * wq) * 2048) + aoff);
        LDSM_X4(ah[4], ah[5], ah[6], ah[7], sb + PA + (uint32_t)((4 * wq + 2) * 2048) + aoff);
        #pragma unroll
        for (int ntp = 0; ntp < 2; ++ntp) {
            const uint32_t boff = (uint32_t)((nqh * 4 + ntp * 2) << 11) + b_lane + (uint32_t)(ks << 8);
            uint32_t b0, b1, b2, b3;
            LDSM_X4(b0, b1, b2, b3, sb + PB_Q + boff);
            MMA_F16(&aQ[((0 * 2 + ntp) * 2 + 0) * 4], ah[0], ah[1], ah[2], ah[3], b0, b1);
            MMA_F16(&aQ[((0 * 2 + ntp) * 2 + 1) * 4], ah[0], ah[1], ah[2], ah[3], b2, b3);
            MMA_F16(&aQ[((1 * 2 + ntp) * 2 + 0) * 4], ah[4], ah[5], ah[6], ah[7], b0, b1);
            MMA_F16(&aQ[((1 * 2 + ntp) * 2 + 1) * 4], ah[4], ah[5], ah[6], ah[7], b2, b3);
            LDSM_X4(b0, b1, b2, b3, sb + PB_K1 + boff);
            MMA_F16(&aK1[((0 * 2 + ntp) * 2 + 0) * 4], ah[0], ah[1], ah[2], ah[3], b0, b1);
            MMA_F16(&aK1[((0 * 2 + ntp) * 2 + 1) * 4], ah[0], ah[1], ah[2], ah[3], b2, b3);
            MMA_F16(&aK1[((1 * 2 + ntp) * 2 + 0) * 4], ah[4], ah[5], ah[6], ah[7], b0, b1);
            MMA_F16(&aK1[((1 * 2 + ntp) * 2 + 1) * 4], ah[4], ah[5], ah[6], ah[7], b2, b3);
            LDSM_X4(b0, b1, b2, b3, sb + PB_K2 + boff);
            MMA_F16(&aK2[((0 * 2 + ntp) * 2 + 0) * 4], ah[0], ah[1], ah[2], ah[3], b0, b1);
            MMA_F16(&aK2[((0 * 2 + ntp) * 2 + 1) * 4], ah[0], ah[1], ah[2], ah[3], b2, b3);
            MMA_F16(&aK2[((1 * 2 + ntp) * 2 + 0) * 4], ah[4], ah[5], ah[6], ah[7], b0, b1);
            MMA_F16(&aK2[((1 * 2 + ntp) * 2 + 1) * 4], ah[4], ah[5], ah[6], ah[7], b2, b3);
        }
    }

    const bool k1sel = ((lane >> 2) < 3);
    const int m = lane >> 2;
    #pragma unroll
    for (int mi = 0; mi < 2; ++mi) {
        #pragma unroll
        for (int ntp = 0; ntp < 2; ++ntp) {
            #pragma unroll
            for (int sub = 0; sub < 2; ++sub) {
                const int g4 = ((mi * 2 + ntp) * 2 + sub) * 4;
                const int rr = r0 + mi * 16;
                const int col = nqh * 32 + ntp * 16 + sub * 8 + cbx;
                const int nodeA = node0 + (rr >> 3);
                const int nodeB = node0 + ((rr + 8) >> 3);
                *(float2*)(g_q + (size_t)nodeA * 512 + m * 64 + col) = make_float2(aQ[g4 + 0], aQ[g4 + 1]);
                *(float2*)(g_q + (size_t)nodeB * 512 + m * 64 + col) = make_float2(aQ[g4 + 2], aQ[g4 + 3]);
                const float k0 = k1sel ? aK1[g4 + 0] : aK2[g4 + 0];
                const float k1 = k1sel ? aK1[g4 + 1] : aK2[g4 + 1];
                const float k2 = k1sel ? aK1[g4 + 2] : aK2[g4 + 2];
                const float k3 = k1sel ? aK1[g4 + 3] : aK2[g4 + 3];
                *(uint32_t*)(g_k + (size_t)nodeA * 512 + m * 64 + col) = pack_f16x2(k0, k1);
                *(uint32_t*)(g_k + (size_t)nodeB * 512 + m * 64 + col) = pack_f16x2(k2, k3);
            }
        }
    }
}

// ------------------------------------------------------------------ kernel 2: warp-specialized persistent main (1024 thr)
__global__ void __launch_bounds__(1024, 1) main_kernel(
    const float* __restrict__ t_ij, const int* __restrict__ nidx,
    const float* __restrict__ lnw, float* __restrict__ out)
{
    extern __shared__ char smem[];
    const uint32_t sb = smem_u32(smem);
    const int tid = threadIdx.x, lane = tid & 31, wid = tid >> 5;

    {
        const char* gsrc = (const char*)g_wtiles;
        #pragma unroll
        for (int i = 0; i < 4; ++i) {
            uint32_t off = (uint32_t)(i * 16384 + tid * 16);
            CP_ASYNC16(sb + SW_E + off, gsrc + off);
        }
        CP_COMMIT();
    }
    const float gl0 = __ldg(lnw + 2 * lane), gl1 = __ldg(lnw + 2 * lane + 1);
    const float gl2 = __ldg(lnw + 64 + 2 * lane), gl3 = __ldg(lnw + 65 + 2 * lane);
    CP_WAIT0();
    __syncthreads();

    const int wq = wid & 3;
    const int nq = (wid >> 2) & 3;
    const uint32_t a_lane = (uint32_t)((((lane >> 3) & 1) << 11) + ((lane >> 4) << 7) + ((lane & 7) << 4));
    const uint32_t b_lane = (uint32_t)(((lane >> 4) << 11) + (((lane >> 3) & 1) << 7) + ((lane & 7) << 4));
    const int r0  = wq * 32 + (lane >> 2);
    const int cbx = (lane & 3) * 2;

    const int nloc = (blockIdx.x < NT_TOTAL) ? ((NT_TOTAL - 1 - (int)blockIdx.x) / (int)gridDim.x + 1) : 0;

    for (int i = 0; i <= nloc; ++i) {
        if (wid >= 16) {
            // ================= LN warps: produce W[i&1] for tile(i), rows (wid-16)*8 .. +7
            if (i < nloc) {
                const int tile = blockIdx.x + i * (int)gridDim.x;
                const int batch = tile >> 10;
                char* wbp = smem + ((i & 1) ? SW_W1 : SW_W0);
                const int m0 = (wid - 16) * 8;
                const int node = tile * 4 + (m0 >> 5);

                const float* qp = g_q + (size_t)node * 512 + 2 * lane;
                float2 q[8];
                #pragma unroll
                for (int m = 0; m < 8; ++m) q[m] = __ldg((const float2*)(qp + m * 64));

                const int* ixp = nidx + tile * 128 + m0;
                const uint32_t* kbase = (const uint32_t*)g_k + (size_t)batch * 4096 * 256 + lane;

                uint32_t kn[8];
                {
                    const uint32_t* kp = kbase + (size_t)__ldg(ixp) * 256;
                    #pragma unroll
                    for (int m = 0; m < 8; ++m) kn[m] = __ldg(kp + m * 32);
                }
                #pragma unroll
                for (int rr = 0; rr < 8; ++rr) {
                    float2 kc[8];
                    #pragma unroll
                    for (int m = 0; m < 8; ++m) kc[m] = h2f2(kn[m]);
                    if (rr < 7) {
                        const uint32_t* kp = kbase + (size_t)__ldg(ixp + rr + 1) * 256;
                        #pragma unroll
                        for (int m = 0; m < 8; ++m) kn[m] = __ldg(kp + m * 32);
                    }
                    float v0 = q[0].x*kc[0].x + q[1].x*kc[1].x + q[2].x*kc[2].x;
                    float v1 = q[0].y*kc[0].y + q[1].y*kc[1].y + q[2].y*kc[2].y;
                    float v2 = q[3].x*kc[3].x + q[4].x*kc[4].x + q[5].x*kc[5].x + q[6].x*kc[6].x + q[7].x*kc[7].x;
                    float v3 = q[3].y*kc[3].y + q[4].y*kc[4].y + q[5].y*kc[5].y + q[6].y*kc[6].y + q[7].y*kc[7].y;
                    float s  = v0 + v1 + v2 + v3;
                    float ss = v0*v0 + v1*v1 + v2*v2 + v3*v3;
                    #pragma unroll
                    for (int o = 16; o > 0; o >>= 1) {
                        s  += __shfl_xor_sync(0xffffffffu, s,  o);
                        ss += __shfl_xor_sync(0xffffffffu, ss, o);
                    }
                    const float mu = s * (1.f / 128.f);
                    const float var = ss * (1.f / 128.f) - mu * mu;
                    const float sc = rsqrtf(fmaxf(var, 0.f) + 1e-5f);
                    v0 = (v0 - mu) * sc * gl0; v1 = (v1 - mu) * sc * gl1;
                    v2 = (v2 - mu) * sc * gl2; v3 = (v3 - mu) * sc * gl3;
                    const int m = m0 + rr;
                    const uint32_t off1 = (uint32_t)(((m >> 3) << 11) + ((m & 7) << 4)
                                                     + ((lane >> 2) << 7) + ((lane & 3) << 2));
                    *(uint32_t*)(wbp + off1)         = pack_f16x2(v0, v1);
                    *(uint32_t*)(wbp + off1 + 1024u) = pack_f16x2(v2, v3);
                }
            }
        } else if (i >= 1) {
            // ================= GEMM warps: consume W[(i-1)&1] for tile(i-1)
            const int tile = blockIdx.x + (i - 1) * (int)gridDim.x;
            const uint32_t wb = sb + (((i - 1) & 1) ? SW_W1 : SW_W0);
            const float* tb = t_ij + (size_t)tile * 16384;
            float* ob = out + (size_t)tile * 16384;

            // ---- stage T (fp32 coalesced -> fp16 blocked smem), GEMM warps only
            #pragma unroll
            for (int it = 0; it < 16; ++it) {
                const int p = it * 512 + tid;           // tid in [0,512)
                const int r = p >> 6, c2 = (p & 63) * 2;
                float2 v = __ldg((const float2*)(tb + r * 128 + c2));
                const uint32_t ao = (uint32_t)(((r >> 3) * 16 + (c2 >> 3)) * 128
                                               + ((r & 7) << 4) + ((c2 & 7) << 1));
                *(uint32_t*)(smem + SW_T + ao) = pack_f16x2(v.x, v.y);
            }
            GEMM_BAR();

            float acc[32];
            #pragma unroll
            for (int z = 0; z < 32; ++z) acc[z] = 0.f;

            // ---- edge GEMM: fp16 (A = normalized W from smem)
            #pragma unroll
            for (int ks = 0; ks < 8; ++ks) {
                uint32_t ah[8];
                const uint32_t aoff = a_lane + (uint32_t)(ks * 256);
                LDSM_X4(ah[0], ah[1], ah[2], ah[3], wb + (uint32_t)((4 * wq) * 2048) + aoff);
                LDSM_X4(ah[4], ah[5], ah[6], ah[7], wb + (uint32_t)((4 * wq + 2) * 2048) + aoff);
                #pragma unroll
                for (int ntp = 0; ntp < 2; ++ntp) {
                    const uint32_t boff = (uint32_t)((nq * 4 + ntp * 2) << 11) + b_lane + (uint32_t)(ks << 8);
                    uint32_t e0, e1, e2, e3;
                    LDSM_X4(e0, e1, e2, e3, sb + SW_E + boff);
                    MMA_F16(&acc[((0 * 2 + ntp) * 2 + 0) * 4], ah[0], ah[1], ah[2], ah[3], e0, e1);
                    MMA_F16(&acc[((0 * 2 + ntp) * 2 + 1) * 4], ah[0], ah[1], ah[2], ah[3], e2, e3);
                    MMA_F16(&acc[((1 * 2 + ntp) * 2 + 0) * 4], ah[4], ah[5], ah[6], ah[7], e0, e1);
                    MMA_F16(&acc[((1 * 2 + ntp) * 2 + 1) * 4], ah[4], ah[5], ah[6], ah[7], e2, e3);
                }
            }
            // ---- sigmoid in place
            #pragma unroll
            for (int z = 0; z < 32; ++z) acc[z] = 1.f / (1.f + __expf(-acc[z]));

            // ---- res GEMM: fp16, A = T fragments from smem
            #pragma unroll
            for (int ks = 0; ks < 8; ++ks) {
                uint32_t th[8];
                const uint32_t aoff = a_lane + (uint32_t)(ks * 256);
                LDSM_X4(th[0], th[1], th[2], th[3], sb + SW_T + (uint32_t)((4 * wq) * 2048) + aoff);
                LDSM_X4(th[4], th[5], th[6], th[7], sb + SW_T + (uint32_t)((4 * wq + 2) * 2048) + aoff);
                #pragma unroll
                for (int ntp = 0; ntp < 2; ++ntp) {
                    const uint32_t boff = (uint32_t)((nq * 4 + ntp * 2) << 11) + b_lane + (uint32_t)(ks << 8);
                    uint32_t b0, b1, b2, b3;
                    LDSM_X4(b0, b1, b2, b3, sb + SW_R + boff);
                    MMA_F16(&acc[((0 * 2 + ntp) * 2 + 0) * 4], th[0], th[1], th[2], th[3], b0, b1);
                    MMA_F16(&acc[((0 * 2 + ntp) * 2 + 1) * 4], th[0], th[1], th[2], th[3], b2, b3);
                    MMA_F16(&acc[((1 * 2 + ntp) * 2 + 0) * 4], th[4], th[5], th[6], th[7], b0, b1);
                    MMA_F16(&acc[((1 * 2 + ntp) * 2 + 1) * 4], th[4], th[5], th[6], th[7], b2, b3);
                }
            }
            // ---- store
            #pragma unroll
            for (int mi = 0; mi < 2; ++mi) {
                #pragma unroll
                for (int ntp = 0; ntp < 2; ++ntp) {
                    #pragma unroll
                    for (int sub = 0; sub < 2; ++sub) {
                        const int g4 = ((mi * 2 + ntp) * 2 + sub) * 4;
                        const int rr = r0 + mi * 16;
                        const int col = nq * 32 + ntp * 16 + sub * 8 + cbx;
                        *(float2*)(ob + rr * 128 + col)       = make_float2(acc[g4 + 0], acc[g4 + 1]);
                        *(float2*)(ob + (rr + 8) * 128 + col) = make_float2(acc[g4 + 2], acc[g4 + 3]);
                    }
                }
            }
        }
        __syncthreads();   // pipeline step: swap W buffers; also fences SW_T reuse
    }
}

// ------------------------------------------------------------------ launch
extern "C" void kernel_launch(void* const* d_in, const int* in_sizes, int n_in,
                              void* d_out, int out_size)
{
    const float* t_ij = (const float*)d_in[0];
    const float* x1   = (const float*)d_in[1];
    const float* x2   = (const float*)d_in[2];
    const int*   nidx = (const int*)  d_in[3];
    const float* tq   = (const float*)d_in[4];
    const float* tk1  = (const float*)d_in[5];
    const float* tk2  = (const float*)d_in[6];
    const float* lnw  = (const float*)d_in[7];
    const float* ew   = (const float*)d_in[8];
    const float* rw   = (const float*)d_in[9];
    float* out = (float*)d_out;

    int dev = 0, nsm = 148;
    cudaGetDevice(&dev);
    cudaDeviceGetAttribute(&nsm, cudaDevAttrMultiProcessorCount, dev);

    cudaFuncSetAttribute(proj_kernel, cudaFuncAttributeMaxDynamicSharedMemorySize, PROJ_SMEM);
    cudaFuncSetAttribute(main_kernel, cudaFuncAttributeMaxDynamicSharedMemorySize, SMEM_B);

    wconv_kernel<<<112, 512>>>(ew, rw, tq, tk1, tk2);
    proj_kernel<<<NNODES / 16, 256, PROJ_SMEM>>>(x1, x2);
    main_kernel<<<nsm, 1024, SMEM_B>>>(t_ij, nidx, lnw, out);
}

// round 17
// speedup vs baseline: 1.4944x; 1.0741x over previous
#include <cuda_runtime.h>
#include <cuda_bf16.h>
#include <cuda_fp16.h>
#include <cstdint>

#define NNODES 8192
#define QK_STRIDE 512
#define NT_TOTAL 2048        // 4 nodes per tile (M=128)

// ------------------------------------------------------------------ scratch
// m-major layout: [node*512 + m*64 + e], m in [0,8), e in [0,64)
__device__ __align__(16) uint16_t g_q[(size_t)NNODES * QK_STRIDE];   // fp16
__device__ __align__(16) uint16_t g_k[(size_t)NNODES * QK_STRIDE];   // fp16
// 2 tile-blocked fp16 weight images, 32KB each: [E][R]
__device__ __align__(16) unsigned char g_wtiles[2 * 32768];
// 3 tile-blocked fp16 projection-weight images, 16KB each: [tq][tk1][tk2]
__device__ __align__(16) unsigned char g_ptiles[3 * 16384];

// ------------------------------------------------------------------ helpers
__device__ __forceinline__ uint32_t smem_u32(const void* p) {
    uint32_t a;
    asm("{ .reg .u64 t; cvta.to.shared.u64 t, %1; cvt.u32.u64 %0, t; }" : "=r"(a) : "l"(p));
    return a;
}
__device__ __forceinline__ uint32_t pack_f16x2(float a, float b) {   // lo=f16(a), hi=f16(b)
    uint32_t p;
    asm("cvt.rn.f16x2.f32 %0, %1, %2;" : "=r"(p) : "f"(b), "f"(a));
    return p;
}
__device__ __forceinline__ float2 h2f2(uint32_t h) {
    return __half22float2(*reinterpret_cast<const __half2*>(&h));
}
#define LDSM_X4(r0, r1, r2, r3, addr) \
    asm volatile("ldmatrix.sync.aligned.m8n8.x4.shared.b16 {%0,%1,%2,%3}, [%4];" \
        : "=r"(r0), "=r"(r1), "=r"(r2), "=r"(r3) : "r"(addr))
#define MMA_F16(c, a0, a1, a2, a3, b0, b1) \
    asm volatile("mma.sync.aligned.m16n8k16.row.col.f32.f16.f16.f32 " \
        "{%0,%1,%2,%3}, {%4,%5,%6,%7}, {%8,%9}, {%0,%1,%2,%3};" \
        : "+f"((c)[0]), "+f"((c)[1]), "+f"((c)[2]), "+f"((c)[3]) \
        : "r"(a0), "r"(a1), "r"(a2), "r"(a3), "r"(b0), "r"(b1))
#define CP_ASYNC16(saddr, gptr) \
    asm volatile("cp.async.cg.shared.global [%0], [%1], 16;" :: "r"(saddr), "l"(gptr))
#define CP_COMMIT() asm volatile("cp.async.commit_group;")
#define CP_WAIT0()  asm volatile("cp.async.wait_group 0;" ::: "memory")
#define GEMM_BAR()  asm volatile("bar.sync 2, 512;" ::: "memory")

// ------------------------------------------------------------------ main smem map (bytes)
#define SW_E   0          // 32768 fp16 edge image
#define SW_R   32768      // 32768 fp16 res image
#define SW_W0  65536      // 32768 fp16 W buf 0 (M=128)
#define SW_W1  98304      // 32768 fp16 W buf 1
#define SW_T   131072     // 32768 fp16 T tile (blocked)
#define SMEM_B 163840

// proj smem map (bytes)
#define PB_Q   0
#define PB_K1  16384
#define PB_K2  32768
#define PA     49152      // 32768 fp16 A tile
#define PRAW   81920      // 65536 raw x (x1: 6144 f32, x2: 10240 f32)
#define PROJ_SMEM 147456

// ------------------------------------------------------------------ kernel 0: weight conversion
__global__ void __launch_bounds__(512) wconv_kernel(
    const float* __restrict__ ew,  const float* __restrict__ rw,
    const float* __restrict__ tq,  const float* __restrict__ tk1,
    const float* __restrict__ tk2)
{
    const int tid = threadIdx.x;
    if (blockIdx.x < 64) {
        int id = blockIdx.x * 512 + tid;
        int w = id >> 14, k = (id >> 7) & 127, n = id & 127;
        float v = (w ? rw : ew)[k * 128 + n];
        uint32_t off = (uint32_t)(((n >> 3) * 8 + (k >> 4)) * 256 + (((k >> 3) & 1) << 7)
                                  + ((n & 7) << 4) + ((k & 7) << 1));
        *(uint16_t*)(g_wtiles + (size_t)w * 32768 + off) = (uint16_t)(pack_f16x2(v, 0.f) & 0xffffu);
    } else {
        int idx = (blockIdx.x - 64) * 512 + tid;      // 0..24575
        int w = idx >> 13;
        int rem = idx & 8191;
        int k = rem >> 6, n = rem & 63;
        const float* src = (w == 0) ? tq : (w == 1) ? tk1 : tk2;
        float v = src[k * 64 + n];
        uint32_t off = (uint32_t)(((n >> 3) * 8 + (k >> 4)) * 256 + (((k >> 3) & 1) << 7)
                                  + ((n & 7) << 4) + ((k & 7) << 1));
        *(uint16_t*)(g_ptiles + (size_t)w * 16384 + off) = (uint16_t)(pack_f16x2(v, 0.f) & 0xffffu);
    }
}

// ------------------------------------------------------------------ kernel 1: projections via tensor cores
__global__ void __launch_bounds__(256) proj_kernel(
    const float* __restrict__ x1, const float* __restrict__ x2)
{
    extern __shared__ char smem[];
    const uint32_t sb = smem_u32(smem);
    const int tid = threadIdx.x, lane = tid & 31, wid = tid >> 5;
    const int node0 = blockIdx.x * 16;

    // ---- stage B images (48 KB) + raw x (64 KB) via cp.async, all coalesced
    #pragma unroll
    for (int i = 0; i < 12; ++i) {
        uint32_t off = (uint32_t)(i * 4096 + tid * 16);
        CP_ASYNC16(sb + off, (const char*)g_ptiles + off);
    }
    {
        const char* gx1 = (const char*)(x1 + (size_t)node0 * 384);   // 24576 B
        const char* gx2 = (const char*)(x2 + (size_t)node0 * 640);   // 40960 B
        #pragma unroll
        for (int i = 0; i < 6; ++i) {
            uint32_t off = (uint32_t)(i * 4096 + tid * 16);
            CP_ASYNC16(sb + PRAW + off, gx1 + off);
        }
        #pragma unroll
        for (int i = 0; i < 10; ++i) {
            uint32_t off = (uint32_t)(i * 4096 + tid * 16);
            CP_ASYNC16(sb + PRAW + 24576u + off, gx2 + off);
        }
    }
    CP_COMMIT();
    CP_WAIT0();
    __syncthreads();

    // ---- convert raw x -> fp16 blocked A (smem -> smem)
    {
        const float* rx1 = (const float*)(smem + PRAW);
        const float* rx2 = rx1 + 6144;
        #pragma unroll 8
        for (int idx = tid; idx < 16384; idx += 256) {
            const int r = idx >> 7, d = idx & 127;
            const int m = r & 7, nl = r >> 3;
            float v = (m < 3) ? rx1[nl * 384 + d * 3 + m]
                              : rx2[nl * 640 + d * 5 + (m - 3)];
            const uint32_t ao = (uint32_t)(((r >> 3) * 16 + (d >> 3)) * 128 + ((r & 7) << 4) + ((d & 7) << 1));
            *(uint16_t*)(smem + PA + ao) = (uint16_t)(pack_f16x2(v, 0.f) & 0xffffu);
        }
    }
    __syncthreads();

    const int wq = wid & 3;
    const int nqh = wid >> 2;
    const uint32_t a_lane = (uint32_t)((((lane >> 3) & 1) << 11) + ((lane >> 4) << 7) + ((lane & 7) << 4));
    const uint32_t b_lane = (uint32_t)(((lane >> 4) << 11) + (((lane >> 3) & 1) << 7) + ((lane & 7) << 4));
    const int r0  = wq * 32 + (lane >> 2);
    const int cbx = (lane & 3) * 2;

    float aQ[32], aK1[32], aK2[32];
    #pragma unroll
    for (int z = 0; z < 32; ++z) { aQ[z] = 0.f; aK1[z] = 0.f; aK2[z] = 0.f; }

    #pragma unroll
    for (int ks = 0; ks < 8; ++ks) {
        uint32_t ah[8];
        const uint32_t aoff = a_lane + (uint32_t)(ks * 256);
        LDSM_X4(ah[0], ah[1], ah[2], ah[3], sb + PA + (uint32_t)((4 * wq) * 2048) + aoff);
        LDSM_X4(ah[4], ah[5], ah[6], ah[7], sb + PA + (uint32_t)((4 * wq + 2) * 2048) + aoff);
        #pragma unroll
        for (int ntp = 0; ntp < 2; ++ntp) {
            const uint32_t boff = (uint32_t)((nqh * 4 + ntp * 2) << 11) + b_lane + (uint32_t)(ks << 8);
            uint32_t b0, b1, b2, b3;
            LDSM_X4(b0, b1, b2, b3, sb + PB_Q + boff);
            MMA_F16(&aQ[((0 * 2 + ntp) * 2 + 0) * 4], ah[0], ah[1], ah[2], ah[3], b0, b1);
            MMA_F16(&aQ[((0 * 2 + ntp) * 2 + 1) * 4], ah[0], ah[1], ah[2], ah[3], b2, b3);
            MMA_F16(&aQ[((1 * 2 + ntp) * 2 + 0) * 4], ah[4], ah[5], ah[6], ah[7], b0, b1);
            MMA_F16(&aQ[((1 * 2 + ntp) * 2 + 1) * 4], ah[4], ah[5], ah[6], ah[7], b2, b3);
            LDSM_X4(b0, b1, b2, b3, sb + PB_K1 + boff);
            MMA_F16(&aK1[((0 * 2 + ntp) * 2 + 0) * 4], ah[0], ah[1], ah[2], ah[3], b0, b1);
            MMA_F16(&aK1[((0 * 2 + ntp) * 2 + 1) * 4], ah[0], ah[1], ah[2], ah[3], b2, b3);
            MMA_F16(&aK1[((1 * 2 + ntp) * 2 + 0) * 4], ah[4], ah[5], ah[6], ah[7], b0, b1);
            MMA_F16(&aK1[((1 * 2 + ntp) * 2 + 1) * 4], ah[4], ah[5], ah[6], ah[7], b2, b3);
            LDSM_X4(b0, b1, b2, b3, sb + PB_K2 + boff);
            MMA_F16(&aK2[((0 * 2 + ntp) * 2 + 0) * 4], ah[0], ah[1], ah[2], ah[3], b0, b1);
            MMA_F16(&aK2[((0 * 2 + ntp) * 2 + 1) * 4], ah[0], ah[1], ah[2], ah[3], b2, b3);
            MMA_F16(&aK2[((1 * 2 + ntp) * 2 + 0) * 4], ah[4], ah[5], ah[6], ah[7], b0, b1);
            MMA_F16(&aK2[((1 * 2 + ntp) * 2 + 1) * 4], ah[4], ah[5], ah[6], ah[7], b2, b3);
        }
    }

    const bool k1sel = ((lane >> 2) < 3);
    const int m = lane >> 2;
    #pragma unroll
    for (int mi = 0; mi < 2; ++mi) {
        #pragma unroll
        for (int ntp = 0; ntp < 2; ++ntp) {
            #pragma unroll
            for (int sub = 0; sub < 2; ++sub) {
                const int g4 = ((mi * 2 + ntp) * 2 + sub) * 4;
                const int rr = r0 + mi * 16;
                const int col = nqh * 32 + ntp * 16 + sub * 8 + cbx;
                const int nodeA = node0 + (rr >> 3);
                const int nodeB = node0 + ((rr + 8) >> 3);
                *(uint32_t*)(g_q + (size_t)nodeA * 512 + m * 64 + col) = pack_f16x2(aQ[g4 + 0], aQ[g4 + 1]);
                *(uint32_t*)(g_q + (size_t)nodeB * 512 + m * 64 + col) = pack_f16x2(aQ[g4 + 2], aQ[g4 + 3]);
                const float k0 = k1sel ? aK1[g4 + 0] : aK2[g4 + 0];
                const float k1 = k1sel ? aK1[g4 + 1] : aK2[g4 + 1];
                const float k2 = k1sel ? aK1[g4 + 2] : aK2[g4 + 2];
                const float k3 = k1sel ? aK1[g4 + 3] : aK2[g4 + 3];
                *(uint32_t*)(g_k + (size_t)nodeA * 512 + m * 64 + col) = pack_f16x2(k0, k1);
                *(uint32_t*)(g_k + (size_t)nodeB * 512 + m * 64 + col) = pack_f16x2(k2, k3);
            }
        }
    }
}

// ------------------------------------------------------------------ kernel 2: warp-specialized persistent main (1024 thr)
__global__ void __launch_bounds__(1024, 1) main_kernel(
    const float* __restrict__ t_ij, const int* __restrict__ nidx,
    const float* __restrict__ lnw, float* __restrict__ out)
{
    extern __shared__ char smem[];
    const uint32_t sb = smem_u32(smem);
    const int tid = threadIdx.x, lane = tid & 31, wid = tid >> 5;

    {
        const char* gsrc = (const char*)g_wtiles;
        #pragma unroll
        for (int i = 0; i < 4; ++i) {
            uint32_t off = (uint32_t)(i * 16384 + tid * 16);
            CP_ASYNC16(sb + SW_E + off, gsrc + off);
        }
        CP_COMMIT();
    }
    const float gl0 = __ldg(lnw + 2 * lane), gl1 = __ldg(lnw + 2 * lane + 1);
    const float gl2 = __ldg(lnw + 64 + 2 * lane), gl3 = __ldg(lnw + 65 + 2 * lane);
    CP_WAIT0();
    __syncthreads();

    const int wq = wid & 3;
    const int nq = (wid >> 2) & 3;
    const uint32_t a_lane = (uint32_t)((((lane >> 3) & 1) << 11) + ((lane >> 4) << 7) + ((lane & 7) << 4));
    const uint32_t b_lane = (uint32_t)(((lane >> 4) << 11) + (((lane >> 3) & 1) << 7) + ((lane & 7) << 4));
    const int r0  = wq * 32 + (lane >> 2);
    const int cbx = (lane & 3) * 2;

    const int nloc = (blockIdx.x < NT_TOTAL) ? ((NT_TOTAL - 1 - (int)blockIdx.x) / (int)gridDim.x + 1) : 0;

    for (int i = 0; i <= nloc; ++i) {
        if (wid >= 16) {
            // ================= LN warps: produce W[i&1] for tile(i), rows (wid-16)*8 .. +7
            if (i < nloc) {
                const int tile = blockIdx.x + i * (int)gridDim.x;
                const int batch = tile >> 10;
                char* wbp = smem + ((i & 1) ? SW_W1 : SW_W0);
                const int m0 = (wid - 16) * 8;
                const int node = tile * 4 + (m0 >> 5);

                const uint32_t* qp = (const uint32_t*)g_q + (size_t)node * 256 + lane;
                float2 q[8];
                #pragma unroll
                for (int m = 0; m < 8; ++m) q[m] = h2f2(__ldg(qp + m * 32));

                const int* ixp = nidx + tile * 128 + m0;
                const uint32_t* kbase = (const uint32_t*)g_k + (size_t)batch * 4096 * 256 + lane;

                uint32_t kn[8];
                {
                    const uint32_t* kp = kbase + (size_t)__ldg(ixp) * 256;
                    #pragma unroll
                    for (int m = 0; m < 8; ++m) kn[m] = __ldg(kp + m * 32);
                }
                #pragma unroll
                for (int rr = 0; rr < 8; ++rr) {
                    float2 kc[8];
                    #pragma unroll
                    for (int m = 0; m < 8; ++m) kc[m] = h2f2(kn[m]);
                    if (rr < 7) {
                        const uint32_t* kp = kbase + (size_t)__ldg(ixp + rr + 1) * 256;
                        #pragma unroll
                        for (int m = 0; m < 8; ++m) kn[m] = __ldg(kp + m * 32);
                    }
                    float v0 = q[0].x*kc[0].x + q[1].x*kc[1].x + q[2].x*kc[2].x;
                    float v1 = q[0].y*kc[0].y + q[1].y*kc[1].y + q[2].y*kc[2].y;
                    float v2 = q[3].x*kc[3].x + q[4].x*kc[4].x + q[5].x*kc[5].x + q[6].x*kc[6].x + q[7].x*kc[7].x;
                    float v3 = q[3].y*kc[3].y + q[4].y*kc[4].y + q[5].y*kc[5].y + q[6].y*kc[6].y + q[7].y*kc[7].y;
                    float s  = v0 + v1 + v2 + v3;
                    float ss = v0*v0 + v1*v1 + v2*v2 + v3*v3;
                    #pragma unroll
                    for (int o = 16; o > 0; o >>= 1) {
                        s  += __shfl_xor_sync(0xffffffffu, s,  o);
                        ss += __shfl_xor_sync(0xffffffffu, ss, o);
                    }
                    const float mu = s * (1.f / 128.f);
                    const float var = ss * (1.f / 128.f) - mu * mu;
                    const float sc = rsqrtf(fmaxf(var, 0.f) + 1e-5f);
                    v0 = (v0 - mu) * sc * gl0; v1 = (v1 - mu) * sc * gl1;
                    v2 = (v2 - mu) * sc * gl2; v3 = (v3 - mu) * sc * gl3;
                    const int m = m0 + rr;
                    const uint32_t off1 = (uint32_t)(((m >> 3) << 11) + ((m & 7) << 4)
                                                     + ((lane >> 2) << 7) + ((lane & 3) << 2));
                    *(uint32_t*)(wbp + off1)         = pack_f16x2(v0, v1);
                    *(uint32_t*)(wbp + off1 + 1024u) = pack_f16x2(v2, v3);
                }
            }
        } else if (i >= 1) {
            // ================= GEMM warps: consume W[(i-1)&1] for tile(i-1)
            const int tile = blockIdx.x + (i - 1) * (int)gridDim.x;
            const uint32_t wb = sb + (((i - 1) & 1) ? SW_W1 : SW_W0);
            const float* tb = t_ij + (size_t)tile * 16384;
            float* ob = out + (size_t)tile * 16384;

            // ---- stage T (fp32 coalesced float4 -> fp16 blocked smem), GEMM warps only
            #pragma unroll
            for (int it = 0; it < 8; ++it) {
                const int p = it * 512 + tid;           // tid in [0,512)
                const int r = p >> 5, c4 = (p & 31) * 4;
                float4 v = __ldg((const float4*)(tb + r * 128 + c4));
                const uint32_t ao = (uint32_t)(((r >> 3) * 16 + (c4 >> 3)) * 128
                                               + ((r & 7) << 4) + ((c4 & 7) << 1));
                *(uint32_t*)(smem + SW_T + ao)      = pack_f16x2(v.x, v.y);
                *(uint32_t*)(smem + SW_T + ao + 4u) = pack_f16x2(v.z, v.w);
            }
            GEMM_BAR();

            float acc[32];
            #pragma unroll
            for (int z = 0; z < 32; ++z) acc[z] = 0.f;

            // ---- edge GEMM: fp16 (A = normalized W from smem)
            #pragma unroll
            for (int ks = 0; ks < 8; ++ks) {
                uint32_t ah[8];
                const uint32_t aoff = a_lane + (uint32_t)(ks * 256);
                LDSM_X4(ah[0], ah[1], ah[2], ah[3], wb + (uint32_t)((4 * wq) * 2048) + aoff);
                LDSM_X4(ah[4], ah[5], ah[6], ah[7], wb + (uint32_t)((4 * wq + 2) * 2048) + aoff);
                #pragma unroll
                for (int ntp = 0; ntp < 2; ++ntp) {
                    const uint32_t boff = (uint32_t)((nq * 4 + ntp * 2) << 11) + b_lane + (uint32_t)(ks << 8);
                    uint32_t e0, e1, e2, e3;
                    LDSM_X4(e0, e1, e2, e3, sb + SW_E + boff);
                    MMA_F16(&acc[((0 * 2 + ntp) * 2 + 0) * 4], ah[0], ah[1], ah[2], ah[3], e0, e1);
                    MMA_F16(&acc[((0 * 2 + ntp) * 2 + 1) * 4], ah[0], ah[1], ah[2], ah[3], e2, e3);
                    MMA_F16(&acc[((1 * 2 + ntp) * 2 + 0) * 4], ah[4], ah[5], ah[6], ah[7], e0, e1);
                    MMA_F16(&acc[((1 * 2 + ntp) * 2 + 1) * 4], ah[4], ah[5], ah[6], ah[7], e2, e3);
                }
            }
            // ---- sigmoid in place
            #pragma unroll
            for (int z = 0; z < 32; ++z) acc[z] = 1.f / (1.f + __expf(-acc[z]));

            // ---- res GEMM: fp16, A = T fragments from smem
            #pragma unroll
            for (int ks = 0; ks < 8; ++ks) {
                uint32_t th[8];
                const uint32_t aoff = a_lane + (uint32_t)(ks * 256);
                LDSM_X4(th[0], th[1], th[2], th[3], sb + SW_T + (uint32_t)((4 * wq) * 2048) + aoff);
                LDSM_X4(th[4], th[5], th[6], th[7], sb + SW_T + (uint32_t)((4 * wq + 2) * 2048) + aoff);
                #pragma unroll
                for (int ntp = 0; ntp < 2; ++ntp) {
                    const uint32_t boff = (uint32_t)((nq * 4 + ntp * 2) << 11) + b_lane + (uint32_t)(ks << 8);
                    uint32_t b0, b1, b2, b3;
                    LDSM_X4(b0, b1, b2, b3, sb + SW_R + boff);
                    MMA_F16(&acc[((0 * 2 + ntp) * 2 + 0) * 4], th[0], th[1], th[2], th[3], b0, b1);
                    MMA_F16(&acc[((0 * 2 + ntp) * 2 + 1) * 4], th[0], th[1], th[2], th[3], b2, b3);
                    MMA_F16(&acc[((1 * 2 + ntp) * 2 + 0) * 4], th[4], th[5], th[6], th[7], b0, b1);
                    MMA_F16(&acc[((1 * 2 + ntp) * 2 + 1) * 4], th[4], th[5], th[6], th[7], b2, b3);
                }
            }
            // ---- store
            #pragma unroll
            for (int mi = 0; mi < 2; ++mi) {
                #pragma unroll
                for (int ntp = 0; ntp < 2; ++ntp) {
                    #pragma unroll
                    for (int sub = 0; sub < 2; ++sub) {
                        const int g4 = ((mi * 2 + ntp) * 2 + sub) * 4;
                        const int rr = r0 + mi * 16;
                        const int col = nq * 32 + ntp * 16 + sub * 8 + cbx;
                        *(float2*)(ob + rr * 128 + col)       = make_float2(acc[g4 + 0], acc[g4 + 1]);
                        *(float2*)(ob + (rr + 8) * 128 + col) = make_float2(acc[g4 + 2], acc[g4 + 3]);
                    }
                }
            }
        }
        __syncthreads();   // pipeline step: swap W buffers; also fences SW_T reuse
    }
}

// ------------------------------------------------------------------ launch
extern "C" void kernel_launch(void* const* d_in, const int* in_sizes, int n_in,
                              void* d_out, int out_size)
{
    const float* t_ij = (const float*)d_in[0];
    const float* x1   = (const float*)d_in[1];
    const float* x2   = (const float*)d_in[2];
    const int*   nidx = (const int*)  d_in[3];
    const float* tq   = (const float*)d_in[4];
    const float* tk1  = (const float*)d_in[5];
    const float* tk2  = (const float*)d_in[6];
    const float* lnw  = (const float*)d_in[7];
    const float* ew   = (const float*)d_in[8];
    const float* rw   = (const float*)d_in[9];
    float* out = (float*)d_out;

    int dev = 0, nsm = 148;
    cudaGetDevice(&dev);
    cudaDeviceGetAttribute(&nsm, cudaDevAttrMultiProcessorCount, dev);

    cudaFuncSetAttribute(proj_kernel, cudaFuncAttributeMaxDynamicSharedMemorySize, PROJ_SMEM);
    cudaFuncSetAttribute(main_kernel, cudaFuncAttributeMaxDynamicSharedMemorySize, SMEM_B);

    wconv_kernel<<<112, 512>>>(ew, rw, tq, tk1, tk2);
    proj_kernel<<<NNODES / 16, 256, PROJ_SMEM>>>(x1, x2);
    main_kernel<<<nsm, 1024, SMEM_B>>>(t_ij, nidx, lnw, out);
}